// round 3
// baseline (speedup 1.0000x reference)
#include <cuda_runtime.h>
#include <math.h>
#include <stdint.h>
#include <stdio.h>

// ---------------- problem constants ----------------
#define NV    50000     // vocab
#define ND    300       // embedding dim
#define NH    16        // heads
#define NVD   16        // value dim per head
#define NQD   200       // additive-attention query dim
#define NT    20        // title length
#define NHIS  50
#define NCDD  5
#define NB    256
#define NREPR 256       // NH*NVD
#define NCOLS 5056      // 4800 (Q: 16 heads x 300) + 256 (EV: 16 heads x 16)
#define QOFF  4800
#define SCALE 0.05773502691896258f   // 1/sqrt(300), used at BOTH attention levels

// ---------------- device scratch (no allocations allowed) ----------------
__device__ float g_w[ND * NCOLS];                 // packed weight matrix [f][col]
__device__ float g_qv[(size_t)NV * NCOLS];        // per-vocab Q & EV table (~1.01 GB)
__device__ float g_reprs[NB * 55 * NREPR];        // [b][n] n<5: cdd reprs, n>=5: his reprs

// =========================================================================
// K0: pack Wq_w [16,300,300] and Wv_w [16,300,16] into g_w [300][5056]
//     col c<4800: h=c/300, e=c%300 -> Wq[h][f][e]
//     col c>=4800: j=c-4800, h=j/16, vd=j%16 -> Wv[h][f][vd]
// =========================================================================
__global__ void k_pack(const float* __restrict__ Wq, const float* __restrict__ Wv)
{
    int idx = blockIdx.x * 256 + threadIdx.x;
    if (idx >= ND * NCOLS) return;
    int f = idx / NCOLS, c = idx % NCOLS;
    float v;
    if (c < QOFF) {
        int h = c / ND, e = c % ND;
        v = Wq[((size_t)h * ND + f) * ND + e];
    } else {
        int j = c - QOFF;
        int h = j >> 4, vd = j & 15;
        v = Wv[((size_t)h * ND + f) * NVD + vd];
    }
    g_w[(size_t)f * NCOLS + c] = v;
}

// =========================================================================
// K1: g_qv[v][c] = sum_f emb[v][f] * g_w[f][c]
//     50000x5056x300 GEMM. 128x128 tile, BK=10, 256 threads, 8x8 microtile.
// =========================================================================
__global__ void __launch_bounds__(256) k_gemm(const float* __restrict__ A)
{
    __shared__ float As[10 * 132];   // [k][m], padded
    __shared__ float Bs[10 * 128];   // [k][n]
    const int c0 = blockIdx.x * 128;
    const int v0 = blockIdx.y * 128;
    const int tid = threadIdx.x;
    const int tx = tid & 15, ty = tid >> 4;
    const int m0 = ty * 8, n0 = tx * 8;

    float acc[8][8];
#pragma unroll
    for (int i = 0; i < 8; i++)
#pragma unroll
        for (int j = 0; j < 8; j++) acc[i][j] = 0.f;

    for (int kt = 0; kt < 30; kt++) {
        const int k0 = kt * 10;
#pragma unroll
        for (int l = 0; l < 5; l++) {
            int i = tid + l * 256;            // 0..1279 -> 128 rows x 10 k
            int m = i / 10, k = i % 10;
            int row = v0 + m;
            As[k * 132 + m] = (row < NV) ? A[(size_t)row * ND + k0 + k] : 0.f;
        }
#pragma unroll
        for (int l = 0; l < 5; l++) {
            int i = tid + l * 256;            // 10 k x 128 n
            int k = i >> 7, nn = i & 127;
            int col = c0 + nn;
            Bs[k * 128 + nn] = (col < NCOLS) ? g_w[(size_t)(k0 + k) * NCOLS + col] : 0.f;
        }
        __syncthreads();
#pragma unroll
        for (int k = 0; k < 10; k++) {
            float a[8], bb[8];
            *(float4*)(a)     = *(const float4*)&As[k * 132 + m0];
            *(float4*)(a + 4) = *(const float4*)&As[k * 132 + m0 + 4];
            *(float4*)(bb)     = *(const float4*)&Bs[k * 128 + n0];
            *(float4*)(bb + 4) = *(const float4*)&Bs[k * 128 + n0 + 4];
#pragma unroll
            for (int i = 0; i < 8; i++)
#pragma unroll
                for (int j = 0; j < 8; j++) acc[i][j] += a[i] * bb[j];
        }
        __syncthreads();
    }
#pragma unroll
    for (int i = 0; i < 8; i++) {
        int row = v0 + m0 + i;
        if (row >= NV) continue;
#pragma unroll
        for (int j = 0; j < 8; j += 4) {
            int col = c0 + n0 + j;
            if (col + 4 <= NCOLS) {
                float4 o = make_float4(acc[i][j], acc[i][j + 1], acc[i][j + 2], acc[i][j + 3]);
                *(float4*)&g_qv[(size_t)row * NCOLS + col] = o;
            }
        }
    }
}

// =========================================================================
// K2: word-level encoder. One CTA per (n, b); n<5 -> candidate, else history.
// smem float offsets:
//   X    [20][300]  @ 0       gathered embeddings
//   XV   [20][256]  @ 6000    gathered EV rows (x@Wv, all heads)
//   QK   [20][300]  @ 11120   per-head gathered Q rows; reused as key [20][200]
//   val  [20][256]  @ 17120
//   attn [20][20]   @ 22240
//   part [8][400]   @ 22640   e-split partial logits
//   wbuf [20]       @ 25840
//   wraw [20]       @ 25860
//   tok  [20] int   @ 25880
// total 25900 floats = 103,600 B  -> 2 CTAs/SM
// =========================================================================
#define WORD_SMEM_BYTES (25900 * 4)

__global__ void __launch_bounds__(256, 2) k_word(
    const int* __restrict__ cand, const int* __restrict__ clk,
    const float* __restrict__ emb,
    const float* __restrict__ Wk, const float* __restrict__ bk,
    const float* __restrict__ qvec)
{
    extern __shared__ float sm[];
    float* X    = sm;
    float* XV   = sm + 6000;
    float* QK   = sm + 11120;
    float* val  = sm + 17120;
    float* attn = sm + 22240;
    float* part = sm + 22640;
    float* wbuf = sm + 25840;
    float* wraw = sm + 25860;
    int*   tok  = (int*)(sm + 25880);

    const int n = blockIdx.x, b = blockIdx.y, tid = threadIdx.x;

    if (tid < NT) {
        tok[tid] = (n < NCDD) ? cand[((size_t)b * NCDD + n) * NT + tid]
                              : clk[((size_t)b * NHIS + (n - NCDD)) * NT + tid];
    }
    __syncthreads();
    for (int i = tid; i < NT * ND; i += 256) {
        int s = i / ND, f = i % ND;
        X[i] = emb[(size_t)tok[s] * ND + f];
    }
    for (int i = tid; i < NT * NREPR; i += 256) {
        int s = i / NREPR, r = i % NREPR;
        XV[i] = g_qv[(size_t)tok[s] * NCOLS + QOFF + r];
    }

    for (int h = 0; h < NH; h++) {
        __syncthreads();   // prior iter's QK/attn/part consumers done
        for (int i = tid; i < NT * ND; i += 256) {
            int s = i / ND, e = i % ND;
            QK[i] = g_qv[(size_t)tok[s] * NCOLS + h * ND + e];
        }
        __syncthreads();
        // blocked bilinear logits: 25 tiles (4s x 4t) x 8 e-chunks = 200 threads
        if (tid < 200) {
            int ec = tid / 25, tile = tid % 25;
            int s0 = (tile / 5) * 4, t0 = (tile % 5) * 4;
            int e0 = ec * 40, e1 = (e0 + 40 < ND) ? e0 + 40 : ND;
            float a4[4][4];
#pragma unroll
            for (int i = 0; i < 4; i++)
#pragma unroll
                for (int j = 0; j < 4; j++) a4[i][j] = 0.f;
            for (int e = e0; e < e1; e += 4) {
                float4 q4[4], x4[4];
#pragma unroll
                for (int i = 0; i < 4; i++) q4[i] = *(const float4*)&QK[(s0 + i) * ND + e];
#pragma unroll
                for (int j = 0; j < 4; j++) x4[j] = *(const float4*)&X[(t0 + j) * ND + e];
#pragma unroll
                for (int i = 0; i < 4; i++)
#pragma unroll
                    for (int j = 0; j < 4; j++)
                        a4[i][j] += q4[i].x * x4[j].x + q4[i].y * x4[j].y
                                  + q4[i].z * x4[j].z + q4[i].w * x4[j].w;
            }
#pragma unroll
            for (int i = 0; i < 4; i++)
#pragma unroll
                for (int j = 0; j < 4; j++)
                    part[ec * 400 + (s0 + i) * NT + (t0 + j)] = a4[i][j];
        }
        __syncthreads();
        for (int idx = tid; idx < 400; idx += 256) {
            float acc = 0.f;
#pragma unroll
            for (int ec = 0; ec < 8; ec++) acc += part[ec * 400 + idx];
            attn[idx] = acc;
        }
        __syncthreads();
        // softmax over t (row-wise), scale by SCALE
        if (tid < NT) {
            float m = -1e30f;
#pragma unroll
            for (int t = 0; t < NT; t++) m = fmaxf(m, attn[tid * NT + t]);
            float tmp[NT], ssum = 0.f;
#pragma unroll
            for (int t = 0; t < NT; t++) { tmp[t] = expf((attn[tid * NT + t] - m) * SCALE); ssum += tmp[t]; }
            float inv = 1.f / ssum;
#pragma unroll
            for (int t = 0; t < NT; t++) attn[tid * NT + t] = tmp[t] * inv;
        }
        __syncthreads();
        // val[s][h*16+vd] = attn @ XV_h
        if (tid < NT * NVD) {
            int s = tid / NVD, vd = tid % NVD;
            float acc = 0.f;
#pragma unroll
            for (int t = 0; t < NT; t++) acc += attn[s * NT + t] * XV[t * NREPR + h * NVD + vd];
            val[s * NREPR + h * NVD + vd] = acc;
        }
    }
    __syncthreads();
    // key = tanh(val @ Wk + bk) -> QK [20][200]   (thread q, 20 accumulators)
    if (tid < NQD) {
        const int q = tid;
        float acc[NT];
#pragma unroll
        for (int s = 0; s < NT; s++) acc[s] = bk[q];
        for (int rb = 0; rb < NREPR; rb += 4) {
            float w0 = __ldg(&Wk[(rb + 0) * NQD + q]);
            float w1 = __ldg(&Wk[(rb + 1) * NQD + q]);
            float w2 = __ldg(&Wk[(rb + 2) * NQD + q]);
            float w3 = __ldg(&Wk[(rb + 3) * NQD + q]);
#pragma unroll
            for (int s = 0; s < NT; s++) {
                float4 v4 = *(const float4*)&val[s * NREPR + rb];
                acc[s] += v4.x * w0 + v4.y * w1 + v4.z * w2 + v4.w * w3;
            }
        }
#pragma unroll
        for (int s = 0; s < NT; s++) QK[s * NQD + q] = tanhf(acc[s]);
    }
    __syncthreads();
    if (tid < NT) {
        float acc = 0.f;
        for (int q = 0; q < NQD; q++) acc += qvec[q] * QK[tid * NQD + q];
        wraw[tid] = acc * SCALE;
    }
    __syncthreads();
    if (tid < NT) {
        float m = -1e30f;
#pragma unroll
        for (int s = 0; s < NT; s++) m = fmaxf(m, wraw[s]);
        float ssum = 0.f;
#pragma unroll
        for (int s = 0; s < NT; s++) ssum += expf(wraw[s] - m);
        wbuf[tid] = expf(wraw[tid] - m) / ssum;
    }
    __syncthreads();
    {
        float acc = 0.f;
#pragma unroll
        for (int s = 0; s < NT; s++) acc += wbuf[s] * val[s * NREPR + tid];
        g_reprs[((size_t)b * 55 + n) * NREPR + tid] = acc;
    }
}

// =========================================================================
// K3: news-level encoder + scorer. One CTA per batch element.
// smem float offsets:
//   X    [50][256] @ 0        his reprs
//   QK   [50][256] @ 12800    per-head q; reused as key [50][200]
//   val  [50][256] @ 25600
//   attn [50][50]  @ 38400
//   xv   [50][16]  @ 40900
//   user [256]     @ 41700
//   score[8]       @ 41956
//   wbuf [50]      @ 41964
//   wraw [50]      @ 42014
// total 42064 floats = 168,256 B  -> 1 CTA/SM
// =========================================================================
#define NEWS_SMEM_BYTES (42064 * 4)

__global__ void __launch_bounds__(256, 1) k_news(
    const float* __restrict__ Wq, const float* __restrict__ Wv,
    const float* __restrict__ Wk, const float* __restrict__ bk,
    const float* __restrict__ qn, float* __restrict__ out)
{
    extern __shared__ float sm[];
    float* X     = sm;
    float* QK    = sm + 12800;
    float* val   = sm + 25600;
    float* attn  = sm + 38400;
    float* xv    = sm + 40900;
    float* user  = sm + 41700;
    float* score = sm + 41956;
    float* wbuf  = sm + 41964;
    float* wraw  = sm + 42014;

    const int b = blockIdx.x, tid = threadIdx.x;

    for (int i = tid; i < NHIS * NREPR; i += 256)
        X[i] = g_reprs[((size_t)b * 55 + NCDD) * NREPR + i];

    for (int h = 0; h < NH; h++) {
        __syncthreads();   // prior iter's QK/attn/xv consumers done; X ready
        // q = X @ Wq_h  (thread owns output column e=tid; f-blocked, X broadcast)
        {
            float acc[NHIS];
#pragma unroll
            for (int s = 0; s < NHIS; s++) acc[s] = 0.f;
            const float* Wh = Wq + (size_t)h * NREPR * NREPR;
            for (int fb = 0; fb < NREPR; fb += 4) {
                float w0 = __ldg(&Wh[(size_t)(fb + 0) * NREPR + tid]);
                float w1 = __ldg(&Wh[(size_t)(fb + 1) * NREPR + tid]);
                float w2 = __ldg(&Wh[(size_t)(fb + 2) * NREPR + tid]);
                float w3 = __ldg(&Wh[(size_t)(fb + 3) * NREPR + tid]);
#pragma unroll 10
                for (int s = 0; s < NHIS; s++) {
                    float4 x4 = *(const float4*)&X[s * NREPR + fb];
                    acc[s] += x4.x * w0 + x4.y * w1 + x4.z * w2 + x4.w * w3;
                }
            }
            for (int s = 0; s < NHIS; s++) QK[s * NREPR + tid] = acc[s];
        }
        __syncthreads();
        // logits: 10x10 tiles of 5x5 -> 100 threads, float4 over e
        if (tid < 100) {
            int s0 = (tid / 10) * 5, t0 = (tid % 10) * 5;
            float a5[5][5];
#pragma unroll
            for (int i = 0; i < 5; i++)
#pragma unroll
                for (int j = 0; j < 5; j++) a5[i][j] = 0.f;
            for (int e = 0; e < NREPR; e += 4) {
                float4 q4[5], x4[5];
#pragma unroll
                for (int i = 0; i < 5; i++) q4[i] = *(const float4*)&QK[(s0 + i) * NREPR + e];
#pragma unroll
                for (int j = 0; j < 5; j++) x4[j] = *(const float4*)&X[(t0 + j) * NREPR + e];
#pragma unroll
                for (int i = 0; i < 5; i++)
#pragma unroll
                    for (int j = 0; j < 5; j++)
                        a5[i][j] += q4[i].x * x4[j].x + q4[i].y * x4[j].y
                                  + q4[i].z * x4[j].z + q4[i].w * x4[j].w;
            }
#pragma unroll
            for (int i = 0; i < 5; i++)
#pragma unroll
                for (int j = 0; j < 5; j++)
                    attn[(s0 + i) * NHIS + (t0 + j)] = a5[i][j];
        }
        __syncthreads();
        if (tid < NHIS) {
            float m = -1e30f;
            for (int t = 0; t < NHIS; t++) m = fmaxf(m, attn[tid * NHIS + t]);
            float ssum = 0.f;
            for (int t = 0; t < NHIS; t++) {
                float e = expf((attn[tid * NHIS + t] - m) * SCALE);
                attn[tid * NHIS + t] = e; ssum += e;
            }
            float inv = 1.f / ssum;
            for (int t = 0; t < NHIS; t++) attn[tid * NHIS + t] *= inv;
        }
        // xv = X @ Wv_h (f-blocked float4; no hazard with softmax above)
        for (int idx = tid; idx < NHIS * NVD; idx += 256) {
            int t = idx / NVD, vd = idx % NVD;
            const float* Wvh = Wv + (size_t)h * NREPR * NVD + vd;
            float acc = 0.f;
            for (int fb = 0; fb < NREPR; fb += 4) {
                float4 x4 = *(const float4*)&X[t * NREPR + fb];
                acc += x4.x * __ldg(&Wvh[(size_t)(fb + 0) * NVD])
                     + x4.y * __ldg(&Wvh[(size_t)(fb + 1) * NVD])
                     + x4.z * __ldg(&Wvh[(size_t)(fb + 2) * NVD])
                     + x4.w * __ldg(&Wvh[(size_t)(fb + 3) * NVD]);
            }
            xv[idx] = acc;
        }
        __syncthreads();
        for (int idx = tid; idx < NHIS * NVD; idx += 256) {
            int s = idx / NVD, vd = idx % NVD;
            float acc = 0.f;
            for (int t = 0; t < NHIS; t++) acc += attn[s * NHIS + t] * xv[t * NVD + vd];
            val[s * NREPR + h * NVD + vd] = acc;
        }
    }
    __syncthreads();
    // key = tanh(val @ Wk_n + bk_n) -> QK [50][200]
    if (tid < NQD) {
        const int q = tid;
        float acc[NHIS];
#pragma unroll
        for (int s = 0; s < NHIS; s++) acc[s] = bk[q];
        for (int rb = 0; rb < NREPR; rb += 4) {
            float w0 = __ldg(&Wk[(rb + 0) * NQD + q]);
            float w1 = __ldg(&Wk[(rb + 1) * NQD + q]);
            float w2 = __ldg(&Wk[(rb + 2) * NQD + q]);
            float w3 = __ldg(&Wk[(rb + 3) * NQD + q]);
#pragma unroll 10
            for (int s = 0; s < NHIS; s++) {
                float4 v4 = *(const float4*)&val[s * NREPR + rb];
                acc[s] += v4.x * w0 + v4.y * w1 + v4.z * w2 + v4.w * w3;
            }
        }
        for (int s = 0; s < NHIS; s++) QK[s * NQD + q] = tanhf(acc[s]);
    }
    __syncthreads();
    if (tid < NHIS) {
        float acc = 0.f;
        for (int q = 0; q < NQD; q++) acc += qn[q] * QK[tid * NQD + q];
        wraw[tid] = acc * SCALE;
    }
    __syncthreads();
    if (tid < NHIS) {
        float m = -1e30f;
        for (int s = 0; s < NHIS; s++) m = fmaxf(m, wraw[s]);
        float ssum = 0.f;
        for (int s = 0; s < NHIS; s++) ssum += expf(wraw[s] - m);
        wbuf[tid] = expf(wraw[tid] - m) / ssum;
    }
    __syncthreads();
    {
        float acc = 0.f;
        for (int s = 0; s < NHIS; s++) acc += wbuf[s] * val[s * NREPR + tid];
        user[tid] = acc;
    }
    __syncthreads();
    // scores vs candidate reprs (warp per candidate), then log_softmax
    {
        const int wid = tid >> 5, lane = tid & 31;
        if (wid < NCDD) {
            float acc = 0.f;
            for (int r = lane; r < NREPR; r += 32)
                acc += g_reprs[((size_t)b * 55 + wid) * NREPR + r] * user[r];
#pragma unroll
            for (int o = 16; o; o >>= 1) acc += __shfl_down_sync(0xffffffffu, acc, o);
            if (lane == 0) score[wid] = acc;
        }
    }
    __syncthreads();
    if (tid < NCDD) {
        float m = -1e30f;
#pragma unroll
        for (int c = 0; c < NCDD; c++) m = fmaxf(m, score[c]);
        float ssum = 0.f;
#pragma unroll
        for (int c = 0; c < NCDD; c++) ssum += expf(score[c] - m);
        out[(size_t)b * NCDD + tid] = score[tid] - m - logf(ssum);
    }
}

// =========================================================================
// launch
// =========================================================================
extern "C" void kernel_launch(void* const* d_in, const int* in_sizes, int n_in,
                              void* d_out, int out_size)
{
    const int*   cand = (const int*)  d_in[0];   // [256,5,20]
    const int*   clk  = (const int*)  d_in[1];   // [256,50,20]
    const float* emb  = (const float*)d_in[2];   // [50000,300]
    const float* Wq_w = (const float*)d_in[3];   // [16,300,300]
    const float* Wv_w = (const float*)d_in[4];   // [16,300,16]
    const float* Wk_w = (const float*)d_in[5];   // [256,200]
    const float* bk_w = (const float*)d_in[6];   // [200]
    const float* qw   = (const float*)d_in[7];   // [200]
    const float* Wq_n = (const float*)d_in[8];   // [16,256,256]
    const float* Wv_n = (const float*)d_in[9];   // [16,256,16]
    const float* Wk_n = (const float*)d_in[10];  // [256,200]
    const float* bk_n = (const float*)d_in[11];  // [200]
    const float* qn   = (const float*)d_in[12];  // [200]
    float* out = (float*)d_out;

    cudaFuncSetAttribute(k_word, cudaFuncAttributeMaxDynamicSharedMemorySize, WORD_SMEM_BYTES);
    cudaFuncSetAttribute(k_news, cudaFuncAttributeMaxDynamicSharedMemorySize, NEWS_SMEM_BYTES);

    k_pack<<<(ND * NCOLS + 255) / 256, 256>>>(Wq_w, Wv_w);
    k_gemm<<<dim3((NCOLS + 127) / 128, (NV + 127) / 128), 256>>>(emb);
    k_word<<<dim3(55, NB), 256, WORD_SMEM_BYTES>>>(cand, clk, emb, Wk_w, bk_w, qw);
    k_news<<<NB, 256, NEWS_SMEM_BYTES>>>(Wq_n, Wv_n, Wk_n, bk_n, qn, out);
}

// round 4
// speedup vs baseline: 2.0010x; 2.0010x over previous
#include <cuda_runtime.h>
#include <math.h>
#include <stdint.h>

// ---------------- problem constants ----------------
#define NV    50000     // vocab
#define ND    300       // embedding dim
#define NH    16        // heads
#define NVD   16        // value dim per head
#define NQD   200       // additive-attention query dim
#define NT    20        // title length
#define NHIS  50
#define NCDD  5
#define NB    256
#define NREPR 256       // NH*NVD
#define NCOLS 5056      // 4800 (Q: 16 heads x 300) + 256 (EV: 16 heads x 16)
#define QOFF  4800
#define SCALE 0.05773502691896258f   // 1/sqrt(300), both attention levels

// ---------------- device scratch ----------------
__device__ float g_w[ND * NCOLS];                 // packed weights [f][col]
__device__ float g_qv[(size_t)NV * NCOLS];        // per-vocab Q & EV table (~1.01 GB)
__device__ float g_reprs[NB * 55 * NREPR];        // [b][n<5: cdd | n>=5: his][256]

// =========================================================================
// K0: pack Wq_w [16,300,300], Wv_w [16,300,16] -> g_w [300][5056]
// =========================================================================
__global__ void k_pack(const float* __restrict__ Wq, const float* __restrict__ Wv)
{
    int idx = blockIdx.x * 256 + threadIdx.x;
    if (idx >= ND * NCOLS) return;
    int f = idx / NCOLS, c = idx % NCOLS;
    float v;
    if (c < QOFF) {
        int h = c / ND, e = c % ND;
        v = Wq[((size_t)h * ND + f) * ND + e];
    } else {
        int j = c - QOFF;
        int h = j >> 4, vd = j & 15;
        v = Wv[((size_t)h * ND + f) * NVD + vd];
    }
    g_w[(size_t)f * NCOLS + c] = v;
}

// =========================================================================
// K1: g_qv = emb @ g_w  (50000 x 5056 x 300)
// 128x128 tile, BK=20 (300 = 15*20), double-buffered smem, 8x8 microtile.
// =========================================================================
#define BK 20
__global__ void __launch_bounds__(256, 2) k_gemm(const float* __restrict__ A)
{
    __shared__ float As[2][BK * 132];   // [k][m], padded stride 132
    __shared__ float Bs[2][BK * 128];   // [k][n]
    const int c0 = blockIdx.x * 128;
    const int v0 = blockIdx.y * 128;
    const int tid = threadIdx.x;
    const int tx = tid & 15, ty = tid >> 4;
    const int m0 = ty * 8, n0 = tx * 8;

    // per-stage load tasks: A = 640 float4 (m = j/5, kq = j%5), B = 640 float4 (k = j>>5, n4 = j&31)
    float4 pa[3], pb[3];

    auto ldg_tile = [&](int kt) {
        const int k0 = kt * BK;
#pragma unroll
        for (int r = 0; r < 3; r++) {
            int j = tid + r * 256;
            if (j < 640) {
                int m = j / 5, kq = j % 5;
                int row = v0 + m;
                pa[r] = (row < NV)
                    ? *(const float4*)&A[(size_t)row * ND + k0 + kq * 4]
                    : make_float4(0.f, 0.f, 0.f, 0.f);
                int k = j >> 5, n4 = j & 31;
                int col = c0 + n4 * 4;
                pb[r] = (col + 3 < NCOLS)
                    ? *(const float4*)&g_w[(size_t)(k0 + k) * NCOLS + col]
                    : make_float4(0.f, 0.f, 0.f, 0.f);
            }
        }
    };
    auto sts_tile = [&](int buf) {
#pragma unroll
        for (int r = 0; r < 3; r++) {
            int j = tid + r * 256;
            if (j < 640) {
                int m = j / 5, kq = j % 5;
                As[buf][(kq * 4 + 0) * 132 + m] = pa[r].x;
                As[buf][(kq * 4 + 1) * 132 + m] = pa[r].y;
                As[buf][(kq * 4 + 2) * 132 + m] = pa[r].z;
                As[buf][(kq * 4 + 3) * 132 + m] = pa[r].w;
                int k = j >> 5, n4 = j & 31;
                *(float4*)&Bs[buf][k * 128 + n4 * 4] = pb[r];
            }
        }
    };

    float acc[8][8];
#pragma unroll
    for (int i = 0; i < 8; i++)
#pragma unroll
        for (int j = 0; j < 8; j++) acc[i][j] = 0.f;

    ldg_tile(0);
    sts_tile(0);
    __syncthreads();

    for (int kt = 0; kt < 15; kt++) {
        const int cur = kt & 1;
        if (kt < 14) ldg_tile(kt + 1);
#pragma unroll
        for (int k = 0; k < BK; k++) {
            float a[8], bb[8];
            *(float4*)(a)      = *(const float4*)&As[cur][k * 132 + m0];
            *(float4*)(a + 4)  = *(const float4*)&As[cur][k * 132 + m0 + 4];
            *(float4*)(bb)     = *(const float4*)&Bs[cur][k * 128 + n0];
            *(float4*)(bb + 4) = *(const float4*)&Bs[cur][k * 128 + n0 + 4];
#pragma unroll
            for (int i = 0; i < 8; i++)
#pragma unroll
                for (int j = 0; j < 8; j++) acc[i][j] += a[i] * bb[j];
        }
        if (kt < 14) sts_tile((kt + 1) & 1);
        __syncthreads();
    }

#pragma unroll
    for (int i = 0; i < 8; i++) {
        int row = v0 + m0 + i;
        if (row >= NV) continue;
#pragma unroll
        for (int j = 0; j < 8; j += 4) {
            int col = c0 + n0 + j;
            if (col + 3 < NCOLS) {
                float4 o = make_float4(acc[i][j], acc[i][j + 1], acc[i][j + 2], acc[i][j + 3]);
                *(float4*)&g_qv[(size_t)row * NCOLS + col] = o;
            }
        }
    }
}

// =========================================================================
// K2: word-level encoder. One CTA per (n, b). Register-lean, no spills.
// smem float offsets:
//   X    [20][300]  @ 0
//   XV   [20][256]  @ 6000
//   Q    [20][300]  @ 11120   (current head; reused as key [20][200] later)
//   val  [20][256]  @ 17120
//   attn [20][20]   @ 22240
//   wraw [20]       @ 22640
//   wbuf [20]       @ 22660
//   tok  [20] int   @ 22680
// total 22700 floats = 90,800 B -> 2 CTAs/SM
// =========================================================================
#define WORD_SMEM_BYTES (22700 * 4)

__global__ void __launch_bounds__(256, 2) k_word(
    const int* __restrict__ cand, const int* __restrict__ clk,
    const float* __restrict__ emb,
    const float* __restrict__ Wk, const float* __restrict__ bk,
    const float* __restrict__ qvec)
{
    extern __shared__ float sm[];
    float* X    = sm;
    float* XV   = sm + 6000;
    float* Q    = sm + 11120;
    float* val  = sm + 17120;
    float* attn = sm + 22240;
    float* wraw = sm + 22640;
    float* wbuf = sm + 22660;
    int*   tok  = (int*)(sm + 22680);

    const int n = blockIdx.x, b = blockIdx.y, tid = threadIdx.x;

    if (tid < NT) {
        tok[tid] = (n < NCDD) ? cand[((size_t)b * NCDD + n) * NT + tid]
                              : clk[((size_t)b * NHIS + (n - NCDD)) * NT + tid];
    }
    __syncthreads();
    // X gather: 20 rows x 75 float4 (emb rows are 1200 B, 16B-aligned)
#pragma unroll 2
    for (int j = tid; j < NT * 75; j += 256) {
        int s = j / 75, o = j % 75;
        ((float4*)X)[s * 75 + o] = ((const float4*)(emb + (size_t)tok[s] * ND))[o];
    }
    // XV gather: 20 rows x 64 float4 from g_qv[tok][4800..5056]
#pragma unroll 2
    for (int j = tid; j < NT * 64; j += 256) {
        int s = j >> 6, o = j & 63;
        ((float4*)XV)[s * 64 + o] =
            ((const float4*)(g_qv + (size_t)tok[s] * NCOLS + QOFF))[o];
    }

    const int tile  = tid >> 3;                 // 0..31 (25 valid)
    const int ec    = tid & 7;                  // e-chunk
    const int valid = (tile < 25);
    const int s0 = valid ? (tile / 5) * 4 : 0;
    const int t0 = valid ? (tile % 5) * 4 : 0;
    const int e0 = ec * 40;
    const int e1 = (e0 + 40 < ND) ? e0 + 40 : ND;

    for (int h = 0; h < NH; h++) {
        __syncthreads();   // prev head's val/attn consumers done before Q/attn overwrite
        // Q gather for head h: 20 rows x 75 float4 (offset h*300 floats = 1200B*h, aligned)
#pragma unroll 2
        for (int j = tid; j < NT * 75; j += 256) {
            int s = j / 75, o = j % 75;
            ((float4*)Q)[s * 75 + o] =
                ((const float4*)(g_qv + (size_t)tok[s] * NCOLS + h * ND))[o];
        }
        __syncthreads();

        // logits: 4x4 (s,t) tile per thread group, e split 8 ways, shfl-reduce
        {
            float a[4][4];
#pragma unroll
            for (int i = 0; i < 4; i++)
#pragma unroll
                for (int j = 0; j < 4; j++) a[i][j] = 0.f;
            for (int e = e0; e < e1; e += 4) {
                float4 q0 = *(const float4*)&Q[(s0 + 0) * ND + e];
                float4 q1 = *(const float4*)&Q[(s0 + 1) * ND + e];
                float4 q2 = *(const float4*)&Q[(s0 + 2) * ND + e];
                float4 q3 = *(const float4*)&Q[(s0 + 3) * ND + e];
#pragma unroll
                for (int j = 0; j < 4; j++) {
                    float4 x = *(const float4*)&X[(t0 + j) * ND + e];
                    a[0][j] += q0.x * x.x + q0.y * x.y + q0.z * x.z + q0.w * x.w;
                    a[1][j] += q1.x * x.x + q1.y * x.y + q1.z * x.z + q1.w * x.w;
                    a[2][j] += q2.x * x.x + q2.y * x.y + q2.z * x.z + q2.w * x.w;
                    a[3][j] += q3.x * x.x + q3.y * x.y + q3.z * x.z + q3.w * x.w;
                }
            }
#pragma unroll
            for (int off = 4; off >= 1; off >>= 1)
#pragma unroll
                for (int i = 0; i < 4; i++)
#pragma unroll
                    for (int j = 0; j < 4; j++)
                        a[i][j] += __shfl_xor_sync(0xffffffffu, a[i][j], off);
            if (ec == 0 && valid) {
#pragma unroll
                for (int i = 0; i < 4; i++)
#pragma unroll
                    for (int j = 0; j < 4; j++)
                        attn[(s0 + i) * NT + (t0 + j)] = a[i][j];
            }
        }
        __syncthreads();

        // softmax over t (rows), with SCALE
        if (tid < NT) {
            float m = -1e30f;
#pragma unroll
            for (int t = 0; t < NT; t++) m = fmaxf(m, attn[tid * NT + t]);
            float ssum = 0.f;
#pragma unroll
            for (int t = 0; t < NT; t++) {
                float e = expf((attn[tid * NT + t] - m) * SCALE);
                attn[tid * NT + t] = e; ssum += e;
            }
            float inv = 1.f / ssum;
#pragma unroll
            for (int t = 0; t < NT; t++) attn[tid * NT + t] *= inv;
        }
        __syncthreads();

        // val[s][h*16+vd] = attn_h @ XV_h  (FIXED: strided over all 320 entries)
        for (int idx = tid; idx < NT * NVD; idx += 256) {
            int s = idx >> 4, vd = idx & 15;
            float acc = 0.f;
#pragma unroll
            for (int t = 0; t < NT; t++)
                acc += attn[s * NT + t] * XV[t * NREPR + h * NVD + vd];
            val[s * NREPR + h * NVD + vd] = acc;
        }
    }
    __syncthreads();

    // key = tanh(val @ Wk + bk) -> Q reused as key [20][200]
    if (tid < NQD) {
        const int q = tid;
        float acc[NT];
        float bq = bk[q];
#pragma unroll
        for (int s = 0; s < NT; s++) acc[s] = bq;
        for (int rb = 0; rb < NREPR; rb += 4) {
            float w0 = __ldg(&Wk[(rb + 0) * NQD + q]);
            float w1 = __ldg(&Wk[(rb + 1) * NQD + q]);
            float w2 = __ldg(&Wk[(rb + 2) * NQD + q]);
            float w3 = __ldg(&Wk[(rb + 3) * NQD + q]);
#pragma unroll
            for (int s = 0; s < NT; s++) {
                float4 v4 = *(const float4*)&val[s * NREPR + rb];
                acc[s] += v4.x * w0 + v4.y * w1 + v4.z * w2 + v4.w * w3;
            }
        }
#pragma unroll
        for (int s = 0; s < NT; s++) Q[s * NQD + q] = tanhf(acc[s]);
    }
    __syncthreads();
    if (tid < NT) {
        float acc = 0.f;
        for (int q = 0; q < NQD; q++) acc += qvec[q] * Q[tid * NQD + q];
        wraw[tid] = acc * SCALE;
    }
    __syncthreads();
    if (tid < NT) {
        float m = -1e30f;
#pragma unroll
        for (int s = 0; s < NT; s++) m = fmaxf(m, wraw[s]);
        float ssum = 0.f;
#pragma unroll
        for (int s = 0; s < NT; s++) ssum += expf(wraw[s] - m);
        wbuf[tid] = expf(wraw[tid] - m) / ssum;
    }
    __syncthreads();
    {
        float acc = 0.f;
#pragma unroll
        for (int s = 0; s < NT; s++) acc += wbuf[s] * val[s * NREPR + tid];
        g_reprs[((size_t)b * 55 + n) * NREPR + tid] = acc;
    }
}

// =========================================================================
// K3: news-level encoder + scorer. One CTA per batch element.
// =========================================================================
#define NEWS_SMEM_BYTES (42064 * 4)

__global__ void __launch_bounds__(256, 1) k_news(
    const float* __restrict__ Wq, const float* __restrict__ Wv,
    const float* __restrict__ Wk, const float* __restrict__ bk,
    const float* __restrict__ qn, float* __restrict__ out)
{
    extern __shared__ float sm[];
    float* X     = sm;
    float* QK    = sm + 12800;
    float* val   = sm + 25600;
    float* attn  = sm + 38400;
    float* xv    = sm + 40900;
    float* user  = sm + 41700;
    float* score = sm + 41956;
    float* wbuf  = sm + 41964;
    float* wraw  = sm + 42014;

    const int b = blockIdx.x, tid = threadIdx.x;

    for (int i = tid; i < NHIS * NREPR; i += 256)
        X[i] = g_reprs[((size_t)b * 55 + NCDD) * NREPR + i];

    for (int h = 0; h < NH; h++) {
        __syncthreads();
        {
            float acc[NHIS];
#pragma unroll
            for (int s = 0; s < NHIS; s++) acc[s] = 0.f;
            const float* Wh = Wq + (size_t)h * NREPR * NREPR;
            for (int fb = 0; fb < NREPR; fb += 4) {
                float w0 = __ldg(&Wh[(size_t)(fb + 0) * NREPR + tid]);
                float w1 = __ldg(&Wh[(size_t)(fb + 1) * NREPR + tid]);
                float w2 = __ldg(&Wh[(size_t)(fb + 2) * NREPR + tid]);
                float w3 = __ldg(&Wh[(size_t)(fb + 3) * NREPR + tid]);
#pragma unroll 10
                for (int s = 0; s < NHIS; s++) {
                    float4 x4 = *(const float4*)&X[s * NREPR + fb];
                    acc[s] += x4.x * w0 + x4.y * w1 + x4.z * w2 + x4.w * w3;
                }
            }
            for (int s = 0; s < NHIS; s++) QK[s * NREPR + tid] = acc[s];
        }
        __syncthreads();
        if (tid < 100) {
            int s0 = (tid / 10) * 5, t0 = (tid % 10) * 5;
            float a5[5][5];
#pragma unroll
            for (int i = 0; i < 5; i++)
#pragma unroll
                for (int j = 0; j < 5; j++) a5[i][j] = 0.f;
            for (int e = 0; e < NREPR; e += 4) {
                float4 q4[5];
#pragma unroll
                for (int i = 0; i < 5; i++) q4[i] = *(const float4*)&QK[(s0 + i) * NREPR + e];
#pragma unroll
                for (int j = 0; j < 5; j++) {
                    float4 x4 = *(const float4*)&X[(t0 + j) * NREPR + e];
#pragma unroll
                    for (int i = 0; i < 5; i++)
                        a5[i][j] += q4[i].x * x4.x + q4[i].y * x4.y
                                  + q4[i].z * x4.z + q4[i].w * x4.w;
                }
            }
#pragma unroll
            for (int i = 0; i < 5; i++)
#pragma unroll
                for (int j = 0; j < 5; j++)
                    attn[(s0 + i) * NHIS + (t0 + j)] = a5[i][j];
        }
        __syncthreads();
        if (tid < NHIS) {
            float m = -1e30f;
            for (int t = 0; t < NHIS; t++) m = fmaxf(m, attn[tid * NHIS + t]);
            float ssum = 0.f;
            for (int t = 0; t < NHIS; t++) {
                float e = expf((attn[tid * NHIS + t] - m) * SCALE);
                attn[tid * NHIS + t] = e; ssum += e;
            }
            float inv = 1.f / ssum;
            for (int t = 0; t < NHIS; t++) attn[tid * NHIS + t] *= inv;
        }
        for (int idx = tid; idx < NHIS * NVD; idx += 256) {
            int t = idx / NVD, vd = idx % NVD;
            const float* Wvh = Wv + (size_t)h * NREPR * NVD + vd;
            float acc = 0.f;
            for (int fb = 0; fb < NREPR; fb += 4) {
                float4 x4 = *(const float4*)&X[t * NREPR + fb];
                acc += x4.x * __ldg(&Wvh[(size_t)(fb + 0) * NVD])
                     + x4.y * __ldg(&Wvh[(size_t)(fb + 1) * NVD])
                     + x4.z * __ldg(&Wvh[(size_t)(fb + 2) * NVD])
                     + x4.w * __ldg(&Wvh[(size_t)(fb + 3) * NVD]);
            }
            xv[idx] = acc;
        }
        __syncthreads();
        for (int idx = tid; idx < NHIS * NVD; idx += 256) {
            int s = idx / NVD, vd = idx % NVD;
            float acc = 0.f;
            for (int t = 0; t < NHIS; t++) acc += attn[s * NHIS + t] * xv[t * NVD + vd];
            val[s * NREPR + h * NVD + vd] = acc;
        }
    }
    __syncthreads();
    if (tid < NQD) {
        const int q = tid;
        float acc[NHIS];
        float bq = bk[q];
#pragma unroll
        for (int s = 0; s < NHIS; s++) acc[s] = bq;
        for (int rb = 0; rb < NREPR; rb += 4) {
            float w0 = __ldg(&Wk[(rb + 0) * NQD + q]);
            float w1 = __ldg(&Wk[(rb + 1) * NQD + q]);
            float w2 = __ldg(&Wk[(rb + 2) * NQD + q]);
            float w3 = __ldg(&Wk[(rb + 3) * NQD + q]);
#pragma unroll 10
            for (int s = 0; s < NHIS; s++) {
                float4 v4 = *(const float4*)&val[s * NREPR + rb];
                acc[s] += v4.x * w0 + v4.y * w1 + v4.z * w2 + v4.w * w3;
            }
        }
        for (int s = 0; s < NHIS; s++) QK[s * NQD + q] = tanhf(acc[s]);
    }
    __syncthreads();
    if (tid < NHIS) {
        float acc = 0.f;
        for (int q = 0; q < NQD; q++) acc += qn[q] * QK[tid * NQD + q];
        wraw[tid] = acc * SCALE;
    }
    __syncthreads();
    if (tid < NHIS) {
        float m = -1e30f;
        for (int s = 0; s < NHIS; s++) m = fmaxf(m, wraw[s]);
        float ssum = 0.f;
        for (int s = 0; s < NHIS; s++) ssum += expf(wraw[s] - m);
        wbuf[tid] = expf(wraw[tid] - m) / ssum;
    }
    __syncthreads();
    {
        float acc = 0.f;
        for (int s = 0; s < NHIS; s++) acc += wbuf[s] * val[s * NREPR + tid];
        user[tid] = acc;
    }
    __syncthreads();
    {
        const int wid = tid >> 5, lane = tid & 31;
        if (wid < NCDD) {
            float acc = 0.f;
            for (int r = lane; r < NREPR; r += 32)
                acc += g_reprs[((size_t)b * 55 + wid) * NREPR + r] * user[r];
#pragma unroll
            for (int o = 16; o; o >>= 1) acc += __shfl_down_sync(0xffffffffu, acc, o);
            if (lane == 0) score[wid] = acc;
        }
    }
    __syncthreads();
    if (tid < NCDD) {
        float m = -1e30f;
#pragma unroll
        for (int c = 0; c < NCDD; c++) m = fmaxf(m, score[c]);
        float ssum = 0.f;
#pragma unroll
        for (int c = 0; c < NCDD; c++) ssum += expf(score[c] - m);
        out[(size_t)b * NCDD + tid] = score[tid] - m - logf(ssum);
    }
}

// =========================================================================
// launch
// =========================================================================
extern "C" void kernel_launch(void* const* d_in, const int* in_sizes, int n_in,
                              void* d_out, int out_size)
{
    const int*   cand = (const int*)  d_in[0];
    const int*   clk  = (const int*)  d_in[1];
    const float* emb  = (const float*)d_in[2];
    const float* Wq_w = (const float*)d_in[3];
    const float* Wv_w = (const float*)d_in[4];
    const float* Wk_w = (const float*)d_in[5];
    const float* bk_w = (const float*)d_in[6];
    const float* qw   = (const float*)d_in[7];
    const float* Wq_n = (const float*)d_in[8];
    const float* Wv_n = (const float*)d_in[9];
    const float* Wk_n = (const float*)d_in[10];
    const float* bk_n = (const float*)d_in[11];
    const float* qn   = (const float*)d_in[12];
    float* out = (float*)d_out;

    cudaFuncSetAttribute(k_word, cudaFuncAttributeMaxDynamicSharedMemorySize, WORD_SMEM_BYTES);
    cudaFuncSetAttribute(k_news, cudaFuncAttributeMaxDynamicSharedMemorySize, NEWS_SMEM_BYTES);

    k_pack<<<(ND * NCOLS + 255) / 256, 256>>>(Wq_w, Wv_w);
    k_gemm<<<dim3((NCOLS + 127) / 128, (NV + 127) / 128), 256>>>(emb);
    k_word<<<dim3(55, NB), 256, WORD_SMEM_BYTES>>>(cand, clk, emb, Wk_w, bk_w, qw);
    k_news<<<NB, 256, NEWS_SMEM_BYTES>>>(Wq_n, Wv_n, Wk_n, bk_n, qn, out);
}

// round 6
// speedup vs baseline: 2.1870x; 1.0930x over previous
#include <cuda_runtime.h>
#include <cuda_bf16.h>
#include <math.h>
#include <stdint.h>

// ---------------- problem constants ----------------
#define NV    50000     // vocab
#define ND    300       // embedding dim
#define NH    16        // heads
#define NVD   16        // value dim per head
#define NQD   200       // additive-attention query dim
#define NT    20        // title length
#define NHIS  50
#define NCDD  5
#define NB    256
#define NREPR 256       // NH*NVD
#define NCOLS 5056      // 4800 (Q: 16 heads x 300) + 256 (EV: 16 heads x 16)
#define QOFF  4800
#define SCALE 0.05773502691896258f   // 1/sqrt(300), both attention levels

// padded GEMM dims (bf16-split folded into K: K' = 3*320 = 960)
#define NVPAD 50048     // 391*128
#define NCPAD 5120      // 40*128
#define KSEG  320       // padded original K
#define KTOT  960       // 3 segments: Ah|Ah|Al  vs  Bh|Bl|Bh
#define TM    128
#define TN    128
#define BKK   32        // k-chunk per stage (960/32 = 30 stages)
#define NSTG  (KTOT / BKK)
#define APAD  40        // smem row stride in bf16 (conflict-free)

// ---------------- device scratch ----------------
__device__ float g_qv[(size_t)NV * NCOLS];             // per-vocab Q & EV table (~1.01 GB)
__device__ float g_reprs[NB * 55 * NREPR];             // [b][n<5: cdd | n>=5: his][256]
__device__ __nv_bfloat16 g_A2[(size_t)NVPAD * KTOT];   // [v][Ah|Ah|Al]   (~96 MB)
__device__ __nv_bfloat16 g_B2[(size_t)NCPAD * KTOT];   // [c][Bh|Bl|Bh]   (~10 MB)

// ---------------- sm_80+ async-copy helpers (valid on plain sm_100 target) ----
__device__ __forceinline__ uint32_t smem_u32(const void* p) {
    uint32_t a;
    asm("{ .reg .u64 t; cvta.to.shared.u64 t, %1; cvt.u32.u64 %0, t; }" : "=r"(a) : "l"(p));
    return a;
}
__device__ __forceinline__ void cp_async16(uint32_t s, const void* g) {
    asm volatile("cp.async.cg.shared.global [%0], [%1], 16;" :: "r"(s), "l"(g));
}
#define CP_COMMIT() asm volatile("cp.async.commit_group;" ::: "memory")
#define CP_WAIT1()  asm volatile("cp.async.wait_group 1;" ::: "memory")
#define CP_WAIT0()  asm volatile("cp.async.wait_group 0;" ::: "memory")

__device__ __forceinline__ void mma16816(float* c, const uint32_t* a, const uint32_t* b) {
    asm volatile(
        "mma.sync.aligned.m16n8k16.row.col.f32.bf16.bf16.f32 "
        "{%0,%1,%2,%3}, {%4,%5,%6,%7}, {%8,%9}, {%0,%1,%2,%3};"
        : "+f"(c[0]), "+f"(c[1]), "+f"(c[2]), "+f"(c[3])
        : "r"(a[0]), "r"(a[1]), "r"(a[2]), "r"(a[3]), "r"(b[0]), "r"(b[1]));
}

// =========================================================================
// K0a: emb fp32 -> g_A2 [NVPAD][960] = [Ah | Ah | Al]
// =========================================================================
__global__ void k_cvt(const float* __restrict__ emb)
{
    size_t idx = (size_t)blockIdx.x * 256 + threadIdx.x;
    if (idx >= (size_t)NVPAD * KTOT) return;
    int v = (int)(idx / KTOT), kk = (int)(idx % KTOT);
    int seg = kk / KSEG, k = kk % KSEG;
    float a = (v < NV && k < ND) ? emb[(size_t)v * ND + k] : 0.f;
    __nv_bfloat16 hi = __float2bfloat16(a);
    if (seg == 2) {
        g_A2[idx] = __float2bfloat16(a - __bfloat162float(hi));
    } else {
        g_A2[idx] = hi;
    }
}

// =========================================================================
// K0b: W^T -> g_B2 [NCPAD][960] = [Bh | Bl | Bh];  B[c][k] = W(f=k, col=c)
// =========================================================================
__global__ void k_packb(const float* __restrict__ Wq, const float* __restrict__ Wv)
{
    size_t idx = (size_t)blockIdx.x * 256 + threadIdx.x;
    if (idx >= (size_t)NCPAD * KTOT) return;
    int c = (int)(idx / KTOT), kk = (int)(idx % KTOT);
    int seg = kk / KSEG, k = kk % KSEG;
    float a = 0.f;
    if (c < NCOLS && k < ND) {
        if (c < QOFF) {
            int h = c / ND, e = c % ND;
            a = Wq[((size_t)h * ND + k) * ND + e];
        } else {
            int j = c - QOFF;
            int h = j >> 4, vd = j & 15;
            a = Wv[((size_t)h * ND + k) * NVD + vd];
        }
    }
    __nv_bfloat16 hi = __float2bfloat16(a);
    if (seg == 1) {
        g_B2[idx] = __float2bfloat16(a - __bfloat162float(hi));
    } else {
        g_B2[idx] = hi;
    }
}

// =========================================================================
// K1: g_qv = A2 @ B2^T via mma.sync bf16 (m16n8k16), cp.async double buffer.
// CTA 128x128, BK=32, 8 warps (4 along m x 2 along n), warp tile 32x64.
// =========================================================================
__global__ void __launch_bounds__(256) k_gemm_mma()
{
    __shared__ __nv_bfloat16 As[2][TM][APAD];
    __shared__ __nv_bfloat16 Bs[2][TN][APAD];

    const int tid = threadIdx.x;
    const int wid = tid >> 5, lid = tid & 31;
    const int wm = wid & 3, wn = wid >> 2;       // 4 x 2 warp grid
    const int g = lid >> 2, t = lid & 3;
    const int c0 = blockIdx.x * TN;
    const int v0 = blockIdx.y * TM;

    // global-load mapping: j in [0,512): row = j>>2, q = j&3 (16B each)
    const int lrow = tid >> 1;                    // 0..127 (2 chunks per row pair)
    // simpler: 512 tasks over 256 threads -> 2 per thread
    auto ldst = [&](int kt) {
        const int buf = kt & 1;
        const size_t k0 = (size_t)kt * BKK;
#pragma unroll
        for (int i = 0; i < 2; i++) {
            int j = tid + i * 256;               // 0..511
            int row = j >> 2, q = j & 3;
            cp_async16(smem_u32(&As[buf][row][q * 8]),
                       g_A2 + (size_t)(v0 + row) * KTOT + k0 + q * 8);
            cp_async16(smem_u32(&Bs[buf][row][q * 8]),
                       g_B2 + (size_t)(c0 + row) * KTOT + k0 + q * 8);
        }
    };

    float acc[2][8][4];
#pragma unroll
    for (int f = 0; f < 2; f++)
#pragma unroll
        for (int n = 0; n < 8; n++)
#pragma unroll
            for (int x = 0; x < 4; x++) acc[f][n][x] = 0.f;

    ldst(0);
    CP_COMMIT();

    for (int kt = 0; kt < NSTG; kt++) {
        const int buf = kt & 1;
        if (kt < NSTG - 1) { ldst(kt + 1); CP_COMMIT(); CP_WAIT1(); }
        else               { CP_WAIT0(); }
        __syncthreads();

#pragma unroll
        for (int ks = 0; ks < BKK; ks += 16) {
            uint32_t af[2][4];
#pragma unroll
            for (int f = 0; f < 2; f++) {
                const int rb = wm * 32 + f * 16;
                af[f][0] = *(const uint32_t*)&As[buf][rb + g][ks + 2 * t];
                af[f][1] = *(const uint32_t*)&As[buf][rb + g + 8][ks + 2 * t];
                af[f][2] = *(const uint32_t*)&As[buf][rb + g][ks + 2 * t + 8];
                af[f][3] = *(const uint32_t*)&As[buf][rb + g + 8][ks + 2 * t + 8];
            }
            uint32_t bf_[8][2];
#pragma unroll
            for (int n = 0; n < 8; n++) {
                const int nb = wn * 64 + n * 8;
                bf_[n][0] = *(const uint32_t*)&Bs[buf][nb + g][ks + 2 * t];
                bf_[n][1] = *(const uint32_t*)&Bs[buf][nb + g][ks + 2 * t + 8];
            }
#pragma unroll
            for (int f = 0; f < 2; f++)
#pragma unroll
                for (int n = 0; n < 8; n++)
                    mma16816(acc[f][n], af[f], bf_[n]);
        }
        __syncthreads();
    }

    // epilogue: fragment layout c0=(g,2t) c1=(g,2t+1) c2=(g+8,2t) c3=(g+8,2t+1)
#pragma unroll
    for (int f = 0; f < 2; f++) {
        const int m = v0 + wm * 32 + f * 16 + g;
#pragma unroll
        for (int n = 0; n < 8; n++) {
            const int col = c0 + wn * 64 + n * 8 + 2 * t;
            if (col < NCOLS) {   // NCOLS even, col even -> pair valid together
                if (m < NV)
                    *(float2*)&g_qv[(size_t)m * NCOLS + col] =
                        make_float2(acc[f][n][0], acc[f][n][1]);
                if (m + 8 < NV)
                    *(float2*)&g_qv[(size_t)(m + 8) * NCOLS + col] =
                        make_float2(acc[f][n][2], acc[f][n][3]);
            }
        }
    }
}

// =========================================================================
// K2: word-level encoder (unchanged from R4 passing version)
// =========================================================================
#define WORD_SMEM_BYTES (22700 * 4)

__global__ void __launch_bounds__(256, 2) k_word(
    const int* __restrict__ cand, const int* __restrict__ clk,
    const float* __restrict__ emb,
    const float* __restrict__ Wk, const float* __restrict__ bk,
    const float* __restrict__ qvec)
{
    extern __shared__ float sm[];
    float* X    = sm;
    float* XV   = sm + 6000;
    float* Q    = sm + 11120;
    float* val  = sm + 17120;
    float* attn = sm + 22240;
    float* wraw = sm + 22640;
    float* wbuf = sm + 22660;
    int*   tok  = (int*)(sm + 22680);

    const int n = blockIdx.x, b = blockIdx.y, tid = threadIdx.x;

    if (tid < NT) {
        tok[tid] = (n < NCDD) ? cand[((size_t)b * NCDD + n) * NT + tid]
                              : clk[((size_t)b * NHIS + (n - NCDD)) * NT + tid];
    }
    __syncthreads();
#pragma unroll 2
    for (int j = tid; j < NT * 75; j += 256) {
        int s = j / 75, o = j % 75;
        ((float4*)X)[s * 75 + o] = ((const float4*)(emb + (size_t)tok[s] * ND))[o];
    }
#pragma unroll 2
    for (int j = tid; j < NT * 64; j += 256) {
        int s = j >> 6, o = j & 63;
        ((float4*)XV)[s * 64 + o] =
            ((const float4*)(g_qv + (size_t)tok[s] * NCOLS + QOFF))[o];
    }

    const int tile  = tid >> 3;
    const int ec    = tid & 7;
    const int valid = (tile < 25);
    const int s0 = valid ? (tile / 5) * 4 : 0;
    const int t0 = valid ? (tile % 5) * 4 : 0;
    const int e0 = ec * 40;
    const int e1 = (e0 + 40 < ND) ? e0 + 40 : ND;

    for (int h = 0; h < NH; h++) {
        __syncthreads();
#pragma unroll 2
        for (int j = tid; j < NT * 75; j += 256) {
            int s = j / 75, o = j % 75;
            ((float4*)Q)[s * 75 + o] =
                ((const float4*)(g_qv + (size_t)tok[s] * NCOLS + h * ND))[o];
        }
        __syncthreads();

        {
            float a[4][4];
#pragma unroll
            for (int i = 0; i < 4; i++)
#pragma unroll
                for (int j = 0; j < 4; j++) a[i][j] = 0.f;
            for (int e = e0; e < e1; e += 4) {
                float4 q0 = *(const float4*)&Q[(s0 + 0) * ND + e];
                float4 q1 = *(const float4*)&Q[(s0 + 1) * ND + e];
                float4 q2 = *(const float4*)&Q[(s0 + 2) * ND + e];
                float4 q3 = *(const float4*)&Q[(s0 + 3) * ND + e];
#pragma unroll
                for (int j = 0; j < 4; j++) {
                    float4 x = *(const float4*)&X[(t0 + j) * ND + e];
                    a[0][j] += q0.x * x.x + q0.y * x.y + q0.z * x.z + q0.w * x.w;
                    a[1][j] += q1.x * x.x + q1.y * x.y + q1.z * x.z + q1.w * x.w;
                    a[2][j] += q2.x * x.x + q2.y * x.y + q2.z * x.z + q2.w * x.w;
                    a[3][j] += q3.x * x.x + q3.y * x.y + q3.z * x.z + q3.w * x.w;
                }
            }
#pragma unroll
            for (int off = 4; off >= 1; off >>= 1)
#pragma unroll
                for (int i = 0; i < 4; i++)
#pragma unroll
                    for (int j = 0; j < 4; j++)
                        a[i][j] += __shfl_xor_sync(0xffffffffu, a[i][j], off);
            if (ec == 0 && valid) {
#pragma unroll
                for (int i = 0; i < 4; i++)
#pragma unroll
                    for (int j = 0; j < 4; j++)
                        attn[(s0 + i) * NT + (t0 + j)] = a[i][j];
            }
        }
        __syncthreads();

        if (tid < NT) {
            float m = -1e30f;
#pragma unroll
            for (int t2 = 0; t2 < NT; t2++) m = fmaxf(m, attn[tid * NT + t2]);
            float ssum = 0.f;
#pragma unroll
            for (int t2 = 0; t2 < NT; t2++) {
                float e = expf((attn[tid * NT + t2] - m) * SCALE);
                attn[tid * NT + t2] = e; ssum += e;
            }
            float inv = 1.f / ssum;
#pragma unroll
            for (int t2 = 0; t2 < NT; t2++) attn[tid * NT + t2] *= inv;
        }
        __syncthreads();

        for (int idx = tid; idx < NT * NVD; idx += 256) {
            int s = idx >> 4, vd = idx & 15;
            float acc = 0.f;
#pragma unroll
            for (int t2 = 0; t2 < NT; t2++)
                acc += attn[s * NT + t2] * XV[t2 * NREPR + h * NVD + vd];
            val[s * NREPR + h * NVD + vd] = acc;
        }
    }
    __syncthreads();

    if (tid < NQD) {
        const int q = tid;
        float acc[NT];
        float bq = bk[q];
#pragma unroll
        for (int s = 0; s < NT; s++) acc[s] = bq;
        for (int rb = 0; rb < NREPR; rb += 4) {
            float w0 = __ldg(&Wk[(rb + 0) * NQD + q]);
            float w1 = __ldg(&Wk[(rb + 1) * NQD + q]);
            float w2 = __ldg(&Wk[(rb + 2) * NQD + q]);
            float w3 = __ldg(&Wk[(rb + 3) * NQD + q]);
#pragma unroll
            for (int s = 0; s < NT; s++) {
                float4 v4 = *(const float4*)&val[s * NREPR + rb];
                acc[s] += v4.x * w0 + v4.y * w1 + v4.z * w2 + v4.w * w3;
            }
        }
#pragma unroll
        for (int s = 0; s < NT; s++) Q[s * NQD + q] = tanhf(acc[s]);
    }
    __syncthreads();
    if (tid < NT) {
        float acc = 0.f;
        for (int q = 0; q < NQD; q++) acc += qvec[q] * Q[tid * NQD + q];
        wraw[tid] = acc * SCALE;
    }
    __syncthreads();
    if (tid < NT) {
        float m = -1e30f;
#pragma unroll
        for (int s = 0; s < NT; s++) m = fmaxf(m, wraw[s]);
        float ssum = 0.f;
#pragma unroll
        for (int s = 0; s < NT; s++) ssum += expf(wraw[s] - m);
        wbuf[tid] = expf(wraw[tid] - m) / ssum;
    }
    __syncthreads();
    {
        float acc = 0.f;
#pragma unroll
        for (int s = 0; s < NT; s++) acc += wbuf[s] * val[s * NREPR + tid];
        g_reprs[((size_t)b * 55 + n) * NREPR + tid] = acc;
    }
}

// =========================================================================
// K3: news-level encoder + scorer (unchanged from R4 passing version)
// =========================================================================
#define NEWS_SMEM_BYTES (42064 * 4)

__global__ void __launch_bounds__(256, 1) k_news(
    const float* __restrict__ Wq, const float* __restrict__ Wv,
    const float* __restrict__ Wk, const float* __restrict__ bk,
    const float* __restrict__ qn, float* __restrict__ out)
{
    extern __shared__ float sm[];
    float* X     = sm;
    float* QK    = sm + 12800;
    float* val   = sm + 25600;
    float* attn  = sm + 38400;
    float* xv    = sm + 40900;
    float* user  = sm + 41700;
    float* score = sm + 41956;
    float* wbuf  = sm + 41964;
    float* wraw  = sm + 42014;

    const int b = blockIdx.x, tid = threadIdx.x;

    for (int i = tid; i < NHIS * NREPR; i += 256)
        X[i] = g_reprs[((size_t)b * 55 + NCDD) * NREPR + i];

    for (int h = 0; h < NH; h++) {
        __syncthreads();
        {
            float acc[NHIS];
#pragma unroll
            for (int s = 0; s < NHIS; s++) acc[s] = 0.f;
            const float* Wh = Wq + (size_t)h * NREPR * NREPR;
            for (int fb = 0; fb < NREPR; fb += 4) {
                float w0 = __ldg(&Wh[(size_t)(fb + 0) * NREPR + tid]);
                float w1 = __ldg(&Wh[(size_t)(fb + 1) * NREPR + tid]);
                float w2 = __ldg(&Wh[(size_t)(fb + 2) * NREPR + tid]);
                float w3 = __ldg(&Wh[(size_t)(fb + 3) * NREPR + tid]);
#pragma unroll 10
                for (int s = 0; s < NHIS; s++) {
                    float4 x4 = *(const float4*)&X[s * NREPR + fb];
                    acc[s] += x4.x * w0 + x4.y * w1 + x4.z * w2 + x4.w * w3;
                }
            }
            for (int s = 0; s < NHIS; s++) QK[s * NREPR + tid] = acc[s];
        }
        __syncthreads();
        if (tid < 100) {
            int s0 = (tid / 10) * 5, t0 = (tid % 10) * 5;
            float a5[5][5];
#pragma unroll
            for (int i = 0; i < 5; i++)
#pragma unroll
                for (int j = 0; j < 5; j++) a5[i][j] = 0.f;
            for (int e = 0; e < NREPR; e += 4) {
                float4 q4[5];
#pragma unroll
                for (int i = 0; i < 5; i++) q4[i] = *(const float4*)&QK[(s0 + i) * NREPR + e];
#pragma unroll
                for (int j = 0; j < 5; j++) {
                    float4 x4 = *(const float4*)&X[(t0 + j) * NREPR + e];
#pragma unroll
                    for (int i = 0; i < 5; i++)
                        a5[i][j] += q4[i].x * x4.x + q4[i].y * x4.y
                                  + q4[i].z * x4.z + q4[i].w * x4.w;
                }
            }
#pragma unroll
            for (int i = 0; i < 5; i++)
#pragma unroll
                for (int j = 0; j < 5; j++)
                    attn[(s0 + i) * NHIS + (t0 + j)] = a5[i][j];
        }
        __syncthreads();
        if (tid < NHIS) {
            float m = -1e30f;
            for (int t = 0; t < NHIS; t++) m = fmaxf(m, attn[tid * NHIS + t]);
            float ssum = 0.f;
            for (int t = 0; t < NHIS; t++) {
                float e = expf((attn[tid * NHIS + t] - m) * SCALE);
                attn[tid * NHIS + t] = e; ssum += e;
            }
            float inv = 1.f / ssum;
            for (int t = 0; t < NHIS; t++) attn[tid * NHIS + t] *= inv;
        }
        for (int idx = tid; idx < NHIS * NVD; idx += 256) {
            int t = idx / NVD, vd = idx % NVD;
            const float* Wvh = Wv + (size_t)h * NREPR * NVD + vd;
            float acc = 0.f;
            for (int fb = 0; fb < NREPR; fb += 4) {
                float4 x4 = *(const float4*)&X[t * NREPR + fb];
                acc += x4.x * __ldg(&Wvh[(size_t)(fb + 0) * NVD])
                     + x4.y * __ldg(&Wvh[(size_t)(fb + 1) * NVD])
                     + x4.z * __ldg(&Wvh[(size_t)(fb + 2) * NVD])
                     + x4.w * __ldg(&Wvh[(size_t)(fb + 3) * NVD]);
            }
            xv[idx] = acc;
        }
        __syncthreads();
        for (int idx = tid; idx < NHIS * NVD; idx += 256) {
            int s = idx / NVD, vd = idx % NVD;
            float acc = 0.f;
            for (int t = 0; t < NHIS; t++) acc += attn[s * NHIS + t] * xv[t * NVD + vd];
            val[s * NREPR + h * NVD + vd] = acc;
        }
    }
    __syncthreads();
    if (tid < NQD) {
        const int q = tid;
        float acc[NHIS];
        float bq = bk[q];
#pragma unroll
        for (int s = 0; s < NHIS; s++) acc[s] = bq;
        for (int rb = 0; rb < NREPR; rb += 4) {
            float w0 = __ldg(&Wk[(rb + 0) * NQD + q]);
            float w1 = __ldg(&Wk[(rb + 1) * NQD + q]);
            float w2 = __ldg(&Wk[(rb + 2) * NQD + q]);
            float w3 = __ldg(&Wk[(rb + 3) * NQD + q]);
#pragma unroll 10
            for (int s = 0; s < NHIS; s++) {
                float4 v4 = *(const float4*)&val[s * NREPR + rb];
                acc[s] += v4.x * w0 + v4.y * w1 + v4.z * w2 + v4.w * w3;
            }
        }
        for (int s = 0; s < NHIS; s++) QK[s * NQD + q] = tanhf(acc[s]);
    }
    __syncthreads();
    if (tid < NHIS) {
        float acc = 0.f;
        for (int q = 0; q < NQD; q++) acc += qn[q] * QK[tid * NQD + q];
        wraw[tid] = acc * SCALE;
    }
    __syncthreads();
    if (tid < NHIS) {
        float m = -1e30f;
        for (int s = 0; s < NHIS; s++) m = fmaxf(m, wraw[s]);
        float ssum = 0.f;
        for (int s = 0; s < NHIS; s++) ssum += expf(wraw[s] - m);
        wbuf[tid] = expf(wraw[tid] - m) / ssum;
    }
    __syncthreads();
    {
        float acc = 0.f;
        for (int s = 0; s < NHIS; s++) acc += wbuf[s] * val[s * NREPR + tid];
        user[tid] = acc;
    }
    __syncthreads();
    {
        const int wid = tid >> 5, lane = tid & 31;
        if (wid < NCDD) {
            float acc = 0.f;
            for (int r = lane; r < NREPR; r += 32)
                acc += g_reprs[((size_t)b * 55 + wid) * NREPR + r] * user[r];
#pragma unroll
            for (int o = 16; o; o >>= 1) acc += __shfl_down_sync(0xffffffffu, acc, o);
            if (lane == 0) score[wid] = acc;
        }
    }
    __syncthreads();
    if (tid < NCDD) {
        float m = -1e30f;
#pragma unroll
        for (int c = 0; c < NCDD; c++) m = fmaxf(m, score[c]);
        float ssum = 0.f;
#pragma unroll
        for (int c = 0; c < NCDD; c++) ssum += expf(score[c] - m);
        out[(size_t)b * NCDD + tid] = score[tid] - m - logf(ssum);
    }
}

// =========================================================================
// launch
// =========================================================================
extern "C" void kernel_launch(void* const* d_in, const int* in_sizes, int n_in,
                              void* d_out, int out_size)
{
    const int*   cand = (const int*)  d_in[0];
    const int*   clk  = (const int*)  d_in[1];
    const float* emb  = (const float*)d_in[2];
    const float* Wq_w = (const float*)d_in[3];
    const float* Wv_w = (const float*)d_in[4];
    const float* Wk_w = (const float*)d_in[5];
    const float* bk_w = (const float*)d_in[6];
    const float* qw   = (const float*)d_in[7];
    const float* Wq_n = (const float*)d_in[8];
    const float* Wv_n = (const float*)d_in[9];
    const float* Wk_n = (const float*)d_in[10];
    const float* bk_n = (const float*)d_in[11];
    const float* qn   = (const float*)d_in[12];
    float* out = (float*)d_out;

    cudaFuncSetAttribute(k_word, cudaFuncAttributeMaxDynamicSharedMemorySize, WORD_SMEM_BYTES);
    cudaFuncSetAttribute(k_news, cudaFuncAttributeMaxDynamicSharedMemorySize, NEWS_SMEM_BYTES);

    k_cvt<<<(int)(((size_t)NVPAD * KTOT + 255) / 256), 256>>>(emb);
    k_packb<<<(int)(((size_t)NCPAD * KTOT + 255) / 256), 256>>>(Wq_w, Wv_w);
    k_gemm_mma<<<dim3(NCPAD / TN, NVPAD / TM), 256>>>();
    k_word<<<dim3(55, NB), 256, WORD_SMEM_BYTES>>>(cand, clk, emb, Wk_w, bk_w, qw);
    k_news<<<NB, 256, NEWS_SMEM_BYTES>>>(Wq_n, Wv_n, Wk_n, bk_n, qn, out);
}

// round 7
// speedup vs baseline: 4.0756x; 1.8636x over previous
#include <cuda_runtime.h>
#include <cuda_bf16.h>
#include <math.h>
#include <stdint.h>

// ---------------- problem constants ----------------
#define NV    50000
#define ND    300
#define NH    16
#define NVD   16
#define NQD   200
#define NT    20
#define NHIS  50
#define NCDD  5
#define NB    256
#define NREPR 256
#define SCALE 0.05773502691896258f   // 1/sqrt(300), both attention levels

// GEMM padded dims
#define NVPAD 50048     // 391*128
#define KSEG  320       // padded K (>=300)
#define KTOT  960       // 3-fold for EV gemm: A=[Ah|Ah|Al], B=[Bh|Bl|Bh]
#define QSTRIDE 304     // per-head padded Q width (bf16)
#define NCQ   4864      // 16*304, = 38*128
#define NCEV  256
#define TM    128
#define TN    128
#define BKK   32
#define APAD  40        // gemm smem row stride (bf16), conflict-free
#define NSTG_Q  (KSEG / BKK)   // 10
#define NSTG_EV (KTOT / BKK)   // 30

// ---------------- device scratch ----------------
__device__ __nv_bfloat16 g_q16[(size_t)NV * NCQ];      // Q table bf16 (~487 MB)
__device__ float         g_ev[(size_t)NV * NCEV];      // EV table fp32 (~51 MB)
__device__ float         g_reprs[NB * 55 * NREPR];
__device__ __nv_bfloat16 g_A2[(size_t)NVPAD * KTOT];   // emb [Ah|Ah|Al] (~96 MB)
__device__ __nv_bfloat16 g_B1[(size_t)NCQ * KSEG];     // Wq^T bf16 [4864][320] (~3 MB)
__device__ __nv_bfloat16 g_B2[(size_t)NCEV * KTOT];    // Wv^T [Bh|Bl|Bh] [256][960]

// ---------------- helpers ----------------
__device__ __forceinline__ uint32_t smem_u32(const void* p) {
    uint32_t a;
    asm("{ .reg .u64 t; cvta.to.shared.u64 t, %1; cvt.u32.u64 %0, t; }" : "=r"(a) : "l"(p));
    return a;
}
__device__ __forceinline__ void cp_async16(uint32_t s, const void* g) {
    asm volatile("cp.async.cg.shared.global [%0], [%1], 16;" :: "r"(s), "l"(g));
}
#define CP_COMMIT() asm volatile("cp.async.commit_group;" ::: "memory")
#define CP_WAIT1()  asm volatile("cp.async.wait_group 1;" ::: "memory")
#define CP_WAIT0()  asm volatile("cp.async.wait_group 0;" ::: "memory")

__device__ __forceinline__ void mma16816(float* c, const uint32_t* a, const uint32_t* b) {
    asm volatile(
        "mma.sync.aligned.m16n8k16.row.col.f32.bf16.bf16.f32 "
        "{%0,%1,%2,%3}, {%4,%5,%6,%7}, {%8,%9}, {%0,%1,%2,%3};"
        : "+f"(c[0]), "+f"(c[1]), "+f"(c[2]), "+f"(c[3])
        : "r"(a[0]), "r"(a[1]), "r"(a[2]), "r"(a[3]), "r"(b[0]), "r"(b[1]));
}

// =========================================================================
// K0a: emb fp32 -> g_A2 [NVPAD][960] = [Ah | Ah | Al]   (32-bit indexing)
// =========================================================================
__global__ void k_cvt(const float* __restrict__ emb)
{
    uint32_t idx = blockIdx.x * 256u + threadIdx.x;
    if (idx >= (uint32_t)NVPAD * KTOT) return;
    uint32_t v = idx / KTOT, kk = idx % KTOT;
    uint32_t seg = kk / KSEG, k = kk % KSEG;
    float a = (v < NV && k < ND) ? emb[(size_t)v * ND + k] : 0.f;
    __nv_bfloat16 hi = __float2bfloat16(a);
    g_A2[idx] = (seg == 2) ? __float2bfloat16(a - __bfloat162float(hi)) : hi;
}

// =========================================================================
// K0b: Wq -> g_B1 [4864][320] bf16 (single precision-level)
//      col c: h=c/304, e=c%304 -> Wq[h][k][e]
// =========================================================================
__global__ void k_packb_q(const float* __restrict__ Wq)
{
    uint32_t idx = blockIdx.x * 256u + threadIdx.x;
    if (idx >= (uint32_t)NCQ * KSEG) return;
    uint32_t c = idx / KSEG, k = idx % KSEG;
    uint32_t h = c / QSTRIDE, e = c % QSTRIDE;
    float a = (e < ND && k < ND) ? Wq[((size_t)h * ND + k) * ND + e] : 0.f;
    g_B1[idx] = __float2bfloat16(a);
}

// =========================================================================
// K0c: Wv -> g_B2 [256][960] = [Bh | Bl | Bh]
// =========================================================================
__global__ void k_packb_ev(const float* __restrict__ Wv)
{
    uint32_t idx = blockIdx.x * 256u + threadIdx.x;
    if (idx >= (uint32_t)NCEV * KTOT) return;
    uint32_t c = idx / KTOT, kk = idx % KTOT;
    uint32_t seg = kk / KSEG, k = kk % KSEG;
    uint32_t h = c >> 4, vd = c & 15;
    float a = (k < ND) ? Wv[((size_t)h * ND + k) * NVD + vd] : 0.f;
    __nv_bfloat16 hi = __float2bfloat16(a);
    g_B2[idx] = (seg == 1) ? __float2bfloat16(a - __bfloat162float(hi)) : hi;
}

// =========================================================================
// K1a: g_q16 = bf16( A(seg0) @ B1^T )  -- 1-fold bf16, K=320
// =========================================================================
__global__ void __launch_bounds__(256) k_gemm_q()
{
    __shared__ __nv_bfloat16 As[2][TM][APAD];
    __shared__ __nv_bfloat16 Bs[2][TN][APAD];
    const int tid = threadIdx.x;
    const int wid = tid >> 5, lid = tid & 31;
    const int wm = wid & 3, wn = wid >> 2;
    const int g = lid >> 2, t = lid & 3;
    const int c0 = blockIdx.x * TN;
    const int v0 = blockIdx.y * TM;

    auto ldst = [&](int kt) {
        const int buf = kt & 1;
        const size_t k0 = (size_t)kt * BKK;
#pragma unroll
        for (int i = 0; i < 2; i++) {
            int j = tid + i * 256;
            int row = j >> 2, q = j & 3;
            cp_async16(smem_u32(&As[buf][row][q * 8]),
                       g_A2 + (size_t)(v0 + row) * KTOT + k0 + q * 8);
            cp_async16(smem_u32(&Bs[buf][row][q * 8]),
                       g_B1 + (size_t)(c0 + row) * KSEG + k0 + q * 8);
        }
    };

    float acc[2][8][4];
#pragma unroll
    for (int f = 0; f < 2; f++)
#pragma unroll
        for (int n = 0; n < 8; n++)
#pragma unroll
            for (int x = 0; x < 4; x++) acc[f][n][x] = 0.f;

    ldst(0);
    CP_COMMIT();
    for (int kt = 0; kt < NSTG_Q; kt++) {
        const int buf = kt & 1;
        if (kt < NSTG_Q - 1) { ldst(kt + 1); CP_COMMIT(); CP_WAIT1(); }
        else                 { CP_WAIT0(); }
        __syncthreads();
#pragma unroll
        for (int ks = 0; ks < BKK; ks += 16) {
            uint32_t af[2][4];
#pragma unroll
            for (int f = 0; f < 2; f++) {
                const int rb = wm * 32 + f * 16;
                af[f][0] = *(const uint32_t*)&As[buf][rb + g][ks + 2 * t];
                af[f][1] = *(const uint32_t*)&As[buf][rb + g + 8][ks + 2 * t];
                af[f][2] = *(const uint32_t*)&As[buf][rb + g][ks + 2 * t + 8];
                af[f][3] = *(const uint32_t*)&As[buf][rb + g + 8][ks + 2 * t + 8];
            }
            uint32_t bf_[8][2];
#pragma unroll
            for (int n = 0; n < 8; n++) {
                const int nb = wn * 64 + n * 8;
                bf_[n][0] = *(const uint32_t*)&Bs[buf][nb + g][ks + 2 * t];
                bf_[n][1] = *(const uint32_t*)&Bs[buf][nb + g][ks + 2 * t + 8];
            }
#pragma unroll
            for (int f = 0; f < 2; f++)
#pragma unroll
                for (int n = 0; n < 8; n++)
                    mma16816(acc[f][n], af[f], bf_[n]);
        }
        __syncthreads();
    }
#pragma unroll
    for (int f = 0; f < 2; f++) {
        const int m = v0 + wm * 32 + f * 16 + g;
#pragma unroll
        for (int n = 0; n < 8; n++) {
            const int col = c0 + wn * 64 + n * 8 + 2 * t;   // even, < NCQ always
            if (m < NV) {
                __nv_bfloat162 pr = __floats2bfloat162_rn(acc[f][n][0], acc[f][n][1]);
                *(__nv_bfloat162*)&g_q16[(size_t)m * NCQ + col] = pr;
            }
            if (m + 8 < NV) {
                __nv_bfloat162 pr = __floats2bfloat162_rn(acc[f][n][2], acc[f][n][3]);
                *(__nv_bfloat162*)&g_q16[(size_t)(m + 8) * NCQ + col] = pr;
            }
        }
    }
}

// =========================================================================
// K1b: g_ev = fp32( A2 @ B2^T )  -- 3-fold split, K=960, N=256
// =========================================================================
__global__ void __launch_bounds__(256) k_gemm_ev()
{
    __shared__ __nv_bfloat16 As[2][TM][APAD];
    __shared__ __nv_bfloat16 Bs[2][TN][APAD];
    const int tid = threadIdx.x;
    const int wid = tid >> 5, lid = tid & 31;
    const int wm = wid & 3, wn = wid >> 2;
    const int g = lid >> 2, t = lid & 3;
    const int c0 = blockIdx.x * TN;
    const int v0 = blockIdx.y * TM;

    auto ldst = [&](int kt) {
        const int buf = kt & 1;
        const size_t k0 = (size_t)kt * BKK;
#pragma unroll
        for (int i = 0; i < 2; i++) {
            int j = tid + i * 256;
            int row = j >> 2, q = j & 3;
            cp_async16(smem_u32(&As[buf][row][q * 8]),
                       g_A2 + (size_t)(v0 + row) * KTOT + k0 + q * 8);
            cp_async16(smem_u32(&Bs[buf][row][q * 8]),
                       g_B2 + (size_t)(c0 + row) * KTOT + k0 + q * 8);
        }
    };

    float acc[2][8][4];
#pragma unroll
    for (int f = 0; f < 2; f++)
#pragma unroll
        for (int n = 0; n < 8; n++)
#pragma unroll
            for (int x = 0; x < 4; x++) acc[f][n][x] = 0.f;

    ldst(0);
    CP_COMMIT();
    for (int kt = 0; kt < NSTG_EV; kt++) {
        const int buf = kt & 1;
        if (kt < NSTG_EV - 1) { ldst(kt + 1); CP_COMMIT(); CP_WAIT1(); }
        else                  { CP_WAIT0(); }
        __syncthreads();
#pragma unroll
        for (int ks = 0; ks < BKK; ks += 16) {
            uint32_t af[2][4];
#pragma unroll
            for (int f = 0; f < 2; f++) {
                const int rb = wm * 32 + f * 16;
                af[f][0] = *(const uint32_t*)&As[buf][rb + g][ks + 2 * t];
                af[f][1] = *(const uint32_t*)&As[buf][rb + g + 8][ks + 2 * t];
                af[f][2] = *(const uint32_t*)&As[buf][rb + g][ks + 2 * t + 8];
                af[f][3] = *(const uint32_t*)&As[buf][rb + g + 8][ks + 2 * t + 8];
            }
            uint32_t bf_[8][2];
#pragma unroll
            for (int n = 0; n < 8; n++) {
                const int nb = wn * 64 + n * 8;
                bf_[n][0] = *(const uint32_t*)&Bs[buf][nb + g][ks + 2 * t];
                bf_[n][1] = *(const uint32_t*)&Bs[buf][nb + g][ks + 2 * t + 8];
            }
#pragma unroll
            for (int f = 0; f < 2; f++)
#pragma unroll
                for (int n = 0; n < 8; n++)
                    mma16816(acc[f][n], af[f], bf_[n]);
        }
        __syncthreads();
    }
#pragma unroll
    for (int f = 0; f < 2; f++) {
        const int m = v0 + wm * 32 + f * 16 + g;
#pragma unroll
        for (int n = 0; n < 8; n++) {
            const int col = c0 + wn * 64 + n * 8 + 2 * t;   // < 256 always
            if (m < NV)
                *(float2*)&g_ev[(size_t)m * NCEV + col] = make_float2(acc[f][n][0], acc[f][n][1]);
            if (m + 8 < NV)
                *(float2*)&g_ev[(size_t)(m + 8) * NCEV + col] = make_float2(acc[f][n][2], acc[f][n][3]);
        }
    }
}

// =========================================================================
// K2: word-level encoder. Logits via mma.sync bf16 (4-head chunks).
// smem byte layout:
//   As   [80][312] bf16 @ 0        (Q tiles for current 4-head chunk; key overlay)
//   Xs   [24][312] bf16 @ 49920    (bf16 embeddings, rows 20-23 zero)
//   XV   [20][256] f32  @ 64896
//   val  [20][256] f32  @ 85376
//   attn [4][20][20] f32 @ 105856
//   wraw [20] @ 112256, wbuf [20] @ 112336, tok [20] int @ 112416
// total 112,496 B
// =========================================================================
#define XSTR 312
#define WORD_SMEM_BYTES 112496

__global__ void __launch_bounds__(256, 2) k_word(
    const int* __restrict__ cand, const int* __restrict__ clk,
    const float* __restrict__ emb,
    const float* __restrict__ Wk, const float* __restrict__ bk,
    const float* __restrict__ qvec)
{
    extern __shared__ char smw[];
    __nv_bfloat16* As = (__nv_bfloat16*)(smw);
    __nv_bfloat16* Xs = (__nv_bfloat16*)(smw + 49920);
    float* XV   = (float*)(smw + 64896);
    float* val  = (float*)(smw + 85376);
    float* attn = (float*)(smw + 105856);
    float* wraw = (float*)(smw + 112256);
    float* wbuf = (float*)(smw + 112336);
    int*   tok  = (int*)(smw + 112416);
    float* key  = (float*)(smw);            // overlay on As after chunks

    const int n = blockIdx.x, b = blockIdx.y, tid = threadIdx.x;
    const int wid = tid >> 5, lid = tid & 31;
    const int g = lid >> 2, t4 = lid & 3;

    if (tid < NT) {
        tok[tid] = (n < NCDD) ? cand[((size_t)b * NCDD + n) * NT + tid]
                              : clk[((size_t)b * NHIS + (n - NCDD)) * NT + tid];
    }
    // zero Xs (rows 20-23 and tail cols must be 0)
    for (int j = tid; j < 24 * XSTR / 4; j += 256)
        ((uint64_t*)Xs)[j] = 0ull;
    __syncthreads();

    // fill Xs rows 0..19 (emb fp32 -> bf16) and XV (g_ev fp32)
    for (int j = tid; j < NT * 75; j += 256) {
        int s = j / 75, o = j % 75;
        float4 v = ((const float4*)(emb + (size_t)tok[s] * ND))[o];
        __nv_bfloat162 p0 = __floats2bfloat162_rn(v.x, v.y);
        __nv_bfloat162 p1 = __floats2bfloat162_rn(v.z, v.w);
        uint2 pk = make_uint2(*(uint32_t*)&p0, *(uint32_t*)&p1);
        *(uint2*)&Xs[s * XSTR + o * 4] = pk;
    }
    for (int j = tid; j < NT * 64; j += 256) {
        int s = j >> 6, o = j & 63;
        ((float4*)(XV + s * NREPR))[o] = ((const float4*)(g_ev + (size_t)tok[s] * NCEV))[o];
    }
    __syncthreads();

    for (int chunk = 0; chunk < 4; chunk++) {
        // gather 4 heads of Q bf16 into As [80][312]
        for (int j = tid; j < 80 * 38; j += 256) {
            int row = j / 38, q = j % 38;
            int s = row % 20, h4 = row / 20;
            const __nv_bfloat16* src =
                g_q16 + (size_t)tok[s] * NCQ + (chunk * 4 + h4) * QSTRIDE;
            *(float4*)&As[row * XSTR + q * 8] = ((const float4*)src)[q];
        }
        __syncthreads();

        // mma: M=80 (5 m16), N=24 (3 n8), K=304 (19 k16); 15 tiles over 8 warps
#pragma unroll
        for (int rep = 0; rep < 2; rep++) {
            int id = wid + rep * 8;
            if (id < 15) {
                int mt = id / 3, nt = id % 3;
                float c4[4] = {0.f, 0.f, 0.f, 0.f};
#pragma unroll
                for (int ks = 0; ks < 19; ks++) {
                    const int kk = ks * 16;
                    uint32_t a[4], bb[2];
                    a[0] = *(const uint32_t*)&As[(mt * 16 + g) * XSTR + kk + 2 * t4];
                    a[1] = *(const uint32_t*)&As[(mt * 16 + g + 8) * XSTR + kk + 2 * t4];
                    a[2] = *(const uint32_t*)&As[(mt * 16 + g) * XSTR + kk + 2 * t4 + 8];
                    a[3] = *(const uint32_t*)&As[(mt * 16 + g + 8) * XSTR + kk + 2 * t4 + 8];
                    bb[0] = *(const uint32_t*)&Xs[(nt * 8 + g) * XSTR + kk + 2 * t4];
                    bb[1] = *(const uint32_t*)&Xs[(nt * 8 + g) * XSTR + kk + 2 * t4 + 8];
                    mma16816(c4, a, bb);
                }
                int r0 = mt * 16 + g, r1 = r0 + 8;
                int col = nt * 8 + 2 * t4;
                if (col < NT) {
                    attn[(r0 / 20) * 400 + (r0 % 20) * NT + col] = c4[0];
                    attn[(r1 / 20) * 400 + (r1 % 20) * NT + col] = c4[2];
                }
                if (col + 1 < NT) {
                    attn[(r0 / 20) * 400 + (r0 % 20) * NT + col + 1] = c4[1];
                    attn[(r1 / 20) * 400 + (r1 % 20) * NT + col + 1] = c4[3];
                }
            }
        }
        __syncthreads();

        // softmax rows (4 heads x 20 s)
        if (tid < 80) {
            float* row = attn + (tid / 20) * 400 + (tid % 20) * NT;
            float m = -1e30f;
#pragma unroll
            for (int t = 0; t < NT; t++) m = fmaxf(m, row[t]);
            float ssum = 0.f;
#pragma unroll
            for (int t = 0; t < NT; t++) {
                float e = expf((row[t] - m) * SCALE);
                row[t] = e; ssum += e;
            }
            float inv = 1.f / ssum;
#pragma unroll
            for (int t = 0; t < NT; t++) row[t] *= inv;
        }
        __syncthreads();

        // val[s][gh*16+vd] = attn_h @ XV_h, 4 heads
        for (int idx = tid; idx < 4 * NT * NVD; idx += 256) {
            int hh = idx / 320, r = idx % 320;
            int s = r >> 4, vd = r & 15;
            int gh = chunk * 4 + hh;
            const float* arow = attn + hh * 400 + s * NT;
            float acc = 0.f;
#pragma unroll
            for (int t = 0; t < NT; t++)
                acc += arow[t] * XV[t * NREPR + gh * NVD + vd];
            val[s * NREPR + gh * NVD + vd] = acc;
        }
        __syncthreads();
    }

    // key = tanh(val @ Wk + bk) -> key [20][200] (overlays As)
    if (tid < NQD) {
        const int q = tid;
        float acc[NT];
        float bq = bk[q];
#pragma unroll
        for (int s = 0; s < NT; s++) acc[s] = bq;
        for (int rb = 0; rb < NREPR; rb += 4) {
            float w0 = __ldg(&Wk[(rb + 0) * NQD + q]);
            float w1 = __ldg(&Wk[(rb + 1) * NQD + q]);
            float w2 = __ldg(&Wk[(rb + 2) * NQD + q]);
            float w3 = __ldg(&Wk[(rb + 3) * NQD + q]);
#pragma unroll
            for (int s = 0; s < NT; s++) {
                float4 v4 = *(const float4*)&val[s * NREPR + rb];
                acc[s] += v4.x * w0 + v4.y * w1 + v4.z * w2 + v4.w * w3;
            }
        }
#pragma unroll
        for (int s = 0; s < NT; s++) key[s * NQD + q] = tanhf(acc[s]);
    }
    __syncthreads();
    if (tid < NT) {
        float acc = 0.f;
        for (int q = 0; q < NQD; q++) acc += qvec[q] * key[tid * NQD + q];
        wraw[tid] = acc * SCALE;
    }
    __syncthreads();
    if (tid < NT) {
        float m = -1e30f;
#pragma unroll
        for (int s = 0; s < NT; s++) m = fmaxf(m, wraw[s]);
        float ssum = 0.f;
#pragma unroll
        for (int s = 0; s < NT; s++) ssum += expf(wraw[s] - m);
        wbuf[tid] = expf(wraw[tid] - m) / ssum;
    }
    __syncthreads();
    {
        float acc = 0.f;
#pragma unroll
        for (int s = 0; s < NT; s++) acc += wbuf[s] * val[s * NREPR + tid];
        g_reprs[((size_t)b * 55 + n) * NREPR + tid] = acc;
    }
}

// =========================================================================
// K3: news-level encoder + scorer (unchanged, passing since R4)
// =========================================================================
#define NEWS_SMEM_BYTES (42064 * 4)

__global__ void __launch_bounds__(256, 1) k_news(
    const float* __restrict__ Wq, const float* __restrict__ Wv,
    const float* __restrict__ Wk, const float* __restrict__ bk,
    const float* __restrict__ qn, float* __restrict__ out)
{
    extern __shared__ float sm[];
    float* X     = sm;
    float* QK    = sm + 12800;
    float* val   = sm + 25600;
    float* attn  = sm + 38400;
    float* xv    = sm + 40900;
    float* user  = sm + 41700;
    float* score = sm + 41956;
    float* wbuf  = sm + 41964;
    float* wraw  = sm + 42014;

    const int b = blockIdx.x, tid = threadIdx.x;

    for (int i = tid; i < NHIS * NREPR; i += 256)
        X[i] = g_reprs[((size_t)b * 55 + NCDD) * NREPR + i];

    for (int h = 0; h < NH; h++) {
        __syncthreads();
        {
            float acc[NHIS];
#pragma unroll
            for (int s = 0; s < NHIS; s++) acc[s] = 0.f;
            const float* Wh = Wq + (size_t)h * NREPR * NREPR;
            for (int fb = 0; fb < NREPR; fb += 4) {
                float w0 = __ldg(&Wh[(size_t)(fb + 0) * NREPR + tid]);
                float w1 = __ldg(&Wh[(size_t)(fb + 1) * NREPR + tid]);
                float w2 = __ldg(&Wh[(size_t)(fb + 2) * NREPR + tid]);
                float w3 = __ldg(&Wh[(size_t)(fb + 3) * NREPR + tid]);
#pragma unroll 10
                for (int s = 0; s < NHIS; s++) {
                    float4 x4 = *(const float4*)&X[s * NREPR + fb];
                    acc[s] += x4.x * w0 + x4.y * w1 + x4.z * w2 + x4.w * w3;
                }
            }
            for (int s = 0; s < NHIS; s++) QK[s * NREPR + tid] = acc[s];
        }
        __syncthreads();
        if (tid < 100) {
            int s0 = (tid / 10) * 5, t0 = (tid % 10) * 5;
            float a5[5][5];
#pragma unroll
            for (int i = 0; i < 5; i++)
#pragma unroll
                for (int j = 0; j < 5; j++) a5[i][j] = 0.f;
            for (int e = 0; e < NREPR; e += 4) {
                float4 q4[5];
#pragma unroll
                for (int i = 0; i < 5; i++) q4[i] = *(const float4*)&QK[(s0 + i) * NREPR + e];
#pragma unroll
                for (int j = 0; j < 5; j++) {
                    float4 x4 = *(const float4*)&X[(t0 + j) * NREPR + e];
#pragma unroll
                    for (int i = 0; i < 5; i++)
                        a5[i][j] += q4[i].x * x4.x + q4[i].y * x4.y
                                  + q4[i].z * x4.z + q4[i].w * x4.w;
                }
            }
#pragma unroll
            for (int i = 0; i < 5; i++)
#pragma unroll
                for (int j = 0; j < 5; j++)
                    attn[(s0 + i) * NHIS + (t0 + j)] = a5[i][j];
        }
        __syncthreads();
        if (tid < NHIS) {
            float m = -1e30f;
            for (int t = 0; t < NHIS; t++) m = fmaxf(m, attn[tid * NHIS + t]);
            float ssum = 0.f;
            for (int t = 0; t < NHIS; t++) {
                float e = expf((attn[tid * NHIS + t] - m) * SCALE);
                attn[tid * NHIS + t] = e; ssum += e;
            }
            float inv = 1.f / ssum;
            for (int t = 0; t < NHIS; t++) attn[tid * NHIS + t] *= inv;
        }
        for (int idx = tid; idx < NHIS * NVD; idx += 256) {
            int t = idx / NVD, vd = idx % NVD;
            const float* Wvh = Wv + (size_t)h * NREPR * NVD + vd;
            float acc = 0.f;
            for (int fb = 0; fb < NREPR; fb += 4) {
                float4 x4 = *(const float4*)&X[t * NREPR + fb];
                acc += x4.x * __ldg(&Wvh[(size_t)(fb + 0) * NVD])
                     + x4.y * __ldg(&Wvh[(size_t)(fb + 1) * NVD])
                     + x4.z * __ldg(&Wvh[(size_t)(fb + 2) * NVD])
                     + x4.w * __ldg(&Wvh[(size_t)(fb + 3) * NVD]);
            }
            xv[idx] = acc;
        }
        __syncthreads();
        for (int idx = tid; idx < NHIS * NVD; idx += 256) {
            int s = idx / NVD, vd = idx % NVD;
            float acc = 0.f;
            for (int t = 0; t < NHIS; t++) acc += attn[s * NHIS + t] * xv[t * NVD + vd];
            val[s * NREPR + h * NVD + vd] = acc;
        }
    }
    __syncthreads();
    if (tid < NQD) {
        const int q = tid;
        float acc[NHIS];
        float bq = bk[q];
#pragma unroll
        for (int s = 0; s < NHIS; s++) acc[s] = bq;
        for (int rb = 0; rb < NREPR; rb += 4) {
            float w0 = __ldg(&Wk[(rb + 0) * NQD + q]);
            float w1 = __ldg(&Wk[(rb + 1) * NQD + q]);
            float w2 = __ldg(&Wk[(rb + 2) * NQD + q]);
            float w3 = __ldg(&Wk[(rb + 3) * NQD + q]);
#pragma unroll 10
            for (int s = 0; s < NHIS; s++) {
                float4 v4 = *(const float4*)&val[s * NREPR + rb];
                acc[s] += v4.x * w0 + v4.y * w1 + v4.z * w2 + v4.w * w3;
            }
        }
        for (int s = 0; s < NHIS; s++) QK[s * NQD + q] = tanhf(acc[s]);
    }
    __syncthreads();
    if (tid < NHIS) {
        float acc = 0.f;
        for (int q = 0; q < NQD; q++) acc += qn[q] * QK[tid * NQD + q];
        wraw[tid] = acc * SCALE;
    }
    __syncthreads();
    if (tid < NHIS) {
        float m = -1e30f;
        for (int s = 0; s < NHIS; s++) m = fmaxf(m, wraw[s]);
        float ssum = 0.f;
        for (int s = 0; s < NHIS; s++) ssum += expf(wraw[s] - m);
        wbuf[tid] = expf(wraw[tid] - m) / ssum;
    }
    __syncthreads();
    {
        float acc = 0.f;
        for (int s = 0; s < NHIS; s++) acc += wbuf[s] * val[s * NREPR + tid];
        user[tid] = acc;
    }
    __syncthreads();
    {
        const int wid2 = tid >> 5, lane = tid & 31;
        if (wid2 < NCDD) {
            float acc = 0.f;
            for (int r = lane; r < NREPR; r += 32)
                acc += g_reprs[((size_t)b * 55 + wid2) * NREPR + r] * user[r];
#pragma unroll
            for (int o = 16; o; o >>= 1) acc += __shfl_down_sync(0xffffffffu, acc, o);
            if (lane == 0) score[wid2] = acc;
        }
    }
    __syncthreads();
    if (tid < NCDD) {
        float m = -1e30f;
#pragma unroll
        for (int c = 0; c < NCDD; c++) m = fmaxf(m, score[c]);
        float ssum = 0.f;
#pragma unroll
        for (int c = 0; c < NCDD; c++) ssum += expf(score[c] - m);
        out[(size_t)b * NCDD + tid] = score[tid] - m - logf(ssum);
    }
}

// =========================================================================
// launch
// =========================================================================
extern "C" void kernel_launch(void* const* d_in, const int* in_sizes, int n_in,
                              void* d_out, int out_size)
{
    const int*   cand = (const int*)  d_in[0];
    const int*   clk  = (const int*)  d_in[1];
    const float* emb  = (const float*)d_in[2];
    const float* Wq_w = (const float*)d_in[3];
    const float* Wv_w = (const float*)d_in[4];
    const float* Wk_w = (const float*)d_in[5];
    const float* bk_w = (const float*)d_in[6];
    const float* qw   = (const float*)d_in[7];
    const float* Wq_n = (const float*)d_in[8];
    const float* Wv_n = (const float*)d_in[9];
    const float* Wk_n = (const float*)d_in[10];
    const float* bk_n = (const float*)d_in[11];
    const float* qn   = (const float*)d_in[12];
    float* out = (float*)d_out;

    cudaFuncSetAttribute(k_word, cudaFuncAttributeMaxDynamicSharedMemorySize, WORD_SMEM_BYTES);
    cudaFuncSetAttribute(k_news, cudaFuncAttributeMaxDynamicSharedMemorySize, NEWS_SMEM_BYTES);

    k_cvt<<<(int)(((size_t)NVPAD * KTOT + 255) / 256), 256>>>(emb);
    k_packb_q<<<(int)(((size_t)NCQ * KSEG + 255) / 256), 256>>>(Wq_w);
    k_packb_ev<<<(int)(((size_t)NCEV * KTOT + 255) / 256), 256>>>(Wv_w);
    k_gemm_q<<<dim3(NCQ / TN, NVPAD / TM), 256>>>();
    k_gemm_ev<<<dim3(NCEV / TN, NVPAD / TM), 256>>>();
    k_word<<<dim3(55, NB), 256, WORD_SMEM_BYTES>>>(cand, clk, emb, Wk_w, bk_w, qw);
    k_news<<<NB, 256, NEWS_SMEM_BYTES>>>(Wq_n, Wv_n, Wk_n, bk_n, qn, out);
}

// round 8
// speedup vs baseline: 5.9182x; 1.4521x over previous
#include <cuda_runtime.h>
#include <cuda_bf16.h>
#include <math.h>
#include <stdint.h>

// ---------------- problem constants ----------------
#define NV    50000
#define ND    300
#define NH    16
#define NVD   16
#define NQD   200
#define NT    20
#define NHIS  50
#define NCDD  5
#define NB    256
#define NREPR 256
#define NSEQ  55            // 5 cdd + 50 his per batch element
#define SCALE 0.05773502691896258f

// GEMM padded dims
#define NVPAD 50048         // 391*128
#define KSEG  320
#define KTOT  960           // [Ah|Ah|Al] vs [Bh|Bl|Bh]
#define QSTRIDE 304
#define NCQ   4864          // 16*304 = 38*128
#define NCEV  256
#define TM    128
#define TN    128
#define BKK   32
#define APAD  40
// news q gemm
#define MN    12800         // 256*50 = 100*128
#define NN    4096          // 16*256 = 32*128
#define KN    256

// ---------------- device scratch ----------------
__device__ __nv_bfloat16 g_q16[(size_t)NV * NCQ];     // word Q table bf16 (~487MB)
__device__ float         g_ev[(size_t)NV * NCEV];     // word EV table fp32 (~51MB)
__device__ float         g_reprs[NB * NSEQ * NREPR];
__device__ float         g_val[(size_t)NB * NSEQ * NT * NREPR];  // word vals (288MB)
__device__ __nv_bfloat16 g_A2[(size_t)NVPAD * KTOT];  // emb [Ah|Ah|Al]
__device__ __nv_bfloat16 g_B1[(size_t)NCQ * KSEG];    // Wq_w^T bf16
__device__ __nv_bfloat16 g_B2[(size_t)NCEV * KTOT];   // Wv_w^T [Bh|Bl|Bh]
__device__ __nv_bfloat16 g_An[(size_t)MN * KN];       // his reprs bf16
__device__ __nv_bfloat16 g_Bn[(size_t)NN * KN];       // Wq_n^T bf16
__device__ __nv_bfloat16 g_qn[(size_t)MN * NN];       // news q table bf16 (~105MB)

// ---------------- helpers ----------------
__device__ __forceinline__ uint32_t smem_u32(const void* p) {
    uint32_t a;
    asm("{ .reg .u64 t; cvta.to.shared.u64 t, %1; cvt.u32.u64 %0, t; }" : "=r"(a) : "l"(p));
    return a;
}
__device__ __forceinline__ void cp_async16(uint32_t s, const void* g) {
    asm volatile("cp.async.cg.shared.global [%0], [%1], 16;" :: "r"(s), "l"(g));
}
#define CP_COMMIT() asm volatile("cp.async.commit_group;" ::: "memory")
#define CP_WAIT1()  asm volatile("cp.async.wait_group 1;" ::: "memory")
#define CP_WAIT0()  asm volatile("cp.async.wait_group 0;" ::: "memory")

__device__ __forceinline__ void mma16816(float* c, const uint32_t* a, const uint32_t* b) {
    asm volatile(
        "mma.sync.aligned.m16n8k16.row.col.f32.bf16.bf16.f32 "
        "{%0,%1,%2,%3}, {%4,%5,%6,%7}, {%8,%9}, {%0,%1,%2,%3};"
        : "+f"(c[0]), "+f"(c[1]), "+f"(c[2]), "+f"(c[3])
        : "r"(a[0]), "r"(a[1]), "r"(a[2]), "r"(a[3]), "r"(b[0]), "r"(b[1]));
}

// =========================================================================
// prep kernels
// =========================================================================
__global__ void k_cvt(const float* __restrict__ emb)
{
    uint32_t idx = blockIdx.x * 256u + threadIdx.x;
    if (idx >= (uint32_t)NVPAD * KTOT) return;
    uint32_t v = idx / KTOT, kk = idx % KTOT;
    uint32_t seg = kk / KSEG, k = kk % KSEG;
    float a = (v < NV && k < ND) ? emb[(size_t)v * ND + k] : 0.f;
    __nv_bfloat16 hi = __float2bfloat16(a);
    g_A2[idx] = (seg == 2) ? __float2bfloat16(a - __bfloat162float(hi)) : hi;
}

__global__ void k_packb_q(const float* __restrict__ Wq)
{
    uint32_t idx = blockIdx.x * 256u + threadIdx.x;
    if (idx >= (uint32_t)NCQ * KSEG) return;
    uint32_t c = idx / KSEG, k = idx % KSEG;
    uint32_t h = c / QSTRIDE, e = c % QSTRIDE;
    float a = (e < ND && k < ND) ? Wq[((size_t)h * ND + k) * ND + e] : 0.f;
    g_B1[idx] = __float2bfloat16(a);
}

__global__ void k_packb_ev(const float* __restrict__ Wv)
{
    uint32_t idx = blockIdx.x * 256u + threadIdx.x;
    if (idx >= (uint32_t)NCEV * KTOT) return;
    uint32_t c = idx / KTOT, kk = idx % KTOT;
    uint32_t seg = kk / KSEG, k = kk % KSEG;
    uint32_t h = c >> 4, vd = c & 15;
    float a = (k < ND) ? Wv[((size_t)h * ND + k) * NVD + vd] : 0.f;
    __nv_bfloat16 hi = __float2bfloat16(a);
    g_B2[idx] = (seg == 1) ? __float2bfloat16(a - __bfloat162float(hi)) : hi;
}

__global__ void k_packb_n(const float* __restrict__ Wqn)
{
    uint32_t idx = blockIdx.x * 256u + threadIdx.x;
    if (idx >= (uint32_t)NN * KN) return;
    uint32_t c = idx / KN, k = idx % KN;
    uint32_t h = c >> 8, e = c & 255;
    g_Bn[idx] = __float2bfloat16(Wqn[((size_t)h * NREPR + k) * NREPR + e]);
}

__global__ void k_cvtrep()
{
    uint32_t idx = blockIdx.x * 256u + threadIdx.x;
    if (idx >= (uint32_t)MN * KN) return;
    uint32_t r = idx / KN, c = idx % KN;
    uint32_t b = r / NHIS, s = r % NHIS;
    g_An[idx] = __float2bfloat16(g_reprs[((size_t)b * NSEQ + NCDD + s) * NREPR + c]);
}

// =========================================================================
// unified tensor-core GEMM (R7-verified skeleton)
// MODE 0: g_q16 = bf16(A2[seg0] @ B1^T)   K=320
// MODE 1: g_ev  = f32 (A2 @ B2^T)         K=960 (3-fold)
// MODE 2: g_qn  = bf16(An @ Bn^T)         K=256
// =========================================================================
template<int MODE>
__global__ void __launch_bounds__(256) k_gemm_t()
{
    constexpr int KA  = (MODE == 2) ? KN : KTOT;
    constexpr int KB  = (MODE == 0) ? KSEG : (MODE == 1) ? KTOT : KN;
    constexpr int NST = (MODE == 0) ? 10 : (MODE == 1) ? 30 : 8;
    const __nv_bfloat16* Ap = (MODE == 2) ? g_An : g_A2;
    const __nv_bfloat16* Bp = (MODE == 0) ? g_B1 : (MODE == 1) ? g_B2 : g_Bn;
    const int maxM = (MODE == 2) ? MN : NV;

    __shared__ __nv_bfloat16 As[2][TM][APAD];
    __shared__ __nv_bfloat16 Bs[2][TN][APAD];
    const int tid = threadIdx.x;
    const int wid = tid >> 5, lid = tid & 31;
    const int wm = wid & 3, wn = wid >> 2;
    const int g = lid >> 2, t = lid & 3;
    const int c0 = blockIdx.x * TN;
    const int v0 = blockIdx.y * TM;

    auto ldst = [&](int kt) {
        const int buf = kt & 1;
        const size_t k0 = (size_t)kt * BKK;
#pragma unroll
        for (int i = 0; i < 2; i++) {
            int j = tid + i * 256;
            int row = j >> 2, q = j & 3;
            cp_async16(smem_u32(&As[buf][row][q * 8]),
                       Ap + (size_t)(v0 + row) * KA + k0 + q * 8);
            cp_async16(smem_u32(&Bs[buf][row][q * 8]),
                       Bp + (size_t)(c0 + row) * KB + k0 + q * 8);
        }
    };

    float acc[2][8][4];
#pragma unroll
    for (int f = 0; f < 2; f++)
#pragma unroll
        for (int n = 0; n < 8; n++)
#pragma unroll
            for (int x = 0; x < 4; x++) acc[f][n][x] = 0.f;

    ldst(0);
    CP_COMMIT();
    for (int kt = 0; kt < NST; kt++) {
        const int buf = kt & 1;
        if (kt < NST - 1) { ldst(kt + 1); CP_COMMIT(); CP_WAIT1(); }
        else              { CP_WAIT0(); }
        __syncthreads();
#pragma unroll
        for (int ks = 0; ks < BKK; ks += 16) {
            uint32_t af[2][4];
#pragma unroll
            for (int f = 0; f < 2; f++) {
                const int rb = wm * 32 + f * 16;
                af[f][0] = *(const uint32_t*)&As[buf][rb + g][ks + 2 * t];
                af[f][1] = *(const uint32_t*)&As[buf][rb + g + 8][ks + 2 * t];
                af[f][2] = *(const uint32_t*)&As[buf][rb + g][ks + 2 * t + 8];
                af[f][3] = *(const uint32_t*)&As[buf][rb + g + 8][ks + 2 * t + 8];
            }
            uint32_t bf_[8][2];
#pragma unroll
            for (int n = 0; n < 8; n++) {
                const int nb = wn * 64 + n * 8;
                bf_[n][0] = *(const uint32_t*)&Bs[buf][nb + g][ks + 2 * t];
                bf_[n][1] = *(const uint32_t*)&Bs[buf][nb + g][ks + 2 * t + 8];
            }
#pragma unroll
            for (int f = 0; f < 2; f++)
#pragma unroll
                for (int n = 0; n < 8; n++)
                    mma16816(acc[f][n], af[f], bf_[n]);
        }
        __syncthreads();
    }

#pragma unroll
    for (int f = 0; f < 2; f++) {
        const int m = v0 + wm * 32 + f * 16 + g;
#pragma unroll
        for (int n = 0; n < 8; n++) {
            const int col = c0 + wn * 64 + n * 8 + 2 * t;
            if (MODE == 1) {
                if (m < maxM)
                    *(float2*)&g_ev[(size_t)m * NCEV + col] = make_float2(acc[f][n][0], acc[f][n][1]);
                if (m + 8 < maxM)
                    *(float2*)&g_ev[(size_t)(m + 8) * NCEV + col] = make_float2(acc[f][n][2], acc[f][n][3]);
            } else {
                __nv_bfloat16* dst = (MODE == 0) ? g_q16 : g_qn;
                const int ldc = (MODE == 0) ? NCQ : NN;
                if (m < maxM) {
                    __nv_bfloat162 pr = __floats2bfloat162_rn(acc[f][n][0], acc[f][n][1]);
                    *(__nv_bfloat162*)&dst[(size_t)m * ldc + col] = pr;
                }
                if (m + 8 < maxM) {
                    __nv_bfloat162 pr = __floats2bfloat162_rn(acc[f][n][2], acc[f][n][3]);
                    *(__nv_bfloat162*)&dst[(size_t)(m + 8) * ldc + col] = pr;
                }
            }
        }
    }
}

// =========================================================================
// k_attn: one CTA per (chunk-of-4-heads, n, b). Writes val slice to g_val.
// smem bytes: As [80][312]bf16 @0 (49920); Xs [24][312]bf16 @49920 (14976);
//             XV [20][64]f32 @64896 (5120); attn [4][20][20]f32 @70016 (6400);
//             tok [20]int @76416. total 76496.
// =========================================================================
#define XSTR 312
#define ATTN_SMEM_BYTES 76496

__global__ void __launch_bounds__(256, 2) k_attn(
    const int* __restrict__ cand, const int* __restrict__ clk,
    const float* __restrict__ emb)
{
    extern __shared__ char smw[];
    __nv_bfloat16* As = (__nv_bfloat16*)(smw);
    __nv_bfloat16* Xs = (__nv_bfloat16*)(smw + 49920);
    float* XV   = (float*)(smw + 64896);
    float* attn = (float*)(smw + 70016);
    int*   tok  = (int*)(smw + 76416);

    const int nx = blockIdx.x;
    const int n = nx >> 2, chunk = nx & 3;
    const int b = blockIdx.y, tid = threadIdx.x;
    const int wid = tid >> 5, lid = tid & 31;
    const int g = lid >> 2, t4 = lid & 3;

    if (tid < NT) {
        tok[tid] = (n < NCDD) ? cand[((size_t)b * NCDD + n) * NT + tid]
                              : clk[((size_t)b * NHIS + (n - NCDD)) * NT + tid];
    }
    for (int j = tid; j < 24 * XSTR / 4; j += 256)
        ((uint64_t*)Xs)[j] = 0ull;
    __syncthreads();

    // Xs rows 0..19 from emb (fp32 -> bf16)
    for (int j = tid; j < NT * 75; j += 256) {
        int s = j / 75, o = j % 75;
        float4 v = ((const float4*)(emb + (size_t)tok[s] * ND))[o];
        __nv_bfloat162 p0 = __floats2bfloat162_rn(v.x, v.y);
        __nv_bfloat162 p1 = __floats2bfloat162_rn(v.z, v.w);
        uint2 pk = make_uint2(*(uint32_t*)&p0, *(uint32_t*)&p1);
        *(uint2*)&Xs[s * XSTR + o * 4] = pk;
    }
    // XV: this chunk's 64 EV columns
    for (int j = tid; j < NT * 16; j += 256) {
        int s = j >> 4, o = j & 15;
        ((float4*)(XV + s * 64))[o] =
            ((const float4*)(g_ev + (size_t)tok[s] * NCEV + chunk * 64))[o];
    }
    // As: 4 heads of Q
    for (int j = tid; j < 80 * 38; j += 256) {
        int row = j / 38, q = j % 38;
        int s = row % 20, h4 = row / 20;
        const __nv_bfloat16* src =
            g_q16 + (size_t)tok[s] * NCQ + (chunk * 4 + h4) * QSTRIDE;
        *(float4*)&As[row * XSTR + q * 8] = ((const float4*)src)[q];
    }
    __syncthreads();

    // logits mma: M=80, N=24, K=304; 15 tiles over 8 warps
#pragma unroll
    for (int rep = 0; rep < 2; rep++) {
        int id = wid + rep * 8;
        if (id < 15) {
            int mt = id / 3, nt = id % 3;
            float c4[4] = {0.f, 0.f, 0.f, 0.f};
#pragma unroll
            for (int ks = 0; ks < 19; ks++) {
                const int kk = ks * 16;
                uint32_t a[4], bb[2];
                a[0] = *(const uint32_t*)&As[(mt * 16 + g) * XSTR + kk + 2 * t4];
                a[1] = *(const uint32_t*)&As[(mt * 16 + g + 8) * XSTR + kk + 2 * t4];
                a[2] = *(const uint32_t*)&As[(mt * 16 + g) * XSTR + kk + 2 * t4 + 8];
                a[3] = *(const uint32_t*)&As[(mt * 16 + g + 8) * XSTR + kk + 2 * t4 + 8];
                bb[0] = *(const uint32_t*)&Xs[(nt * 8 + g) * XSTR + kk + 2 * t4];
                bb[1] = *(const uint32_t*)&Xs[(nt * 8 + g) * XSTR + kk + 2 * t4 + 8];
                mma16816(c4, a, bb);
            }
            int r0 = mt * 16 + g, r1 = r0 + 8;
            int col = nt * 8 + 2 * t4;
            if (col < NT) {
                attn[(r0 / 20) * 400 + (r0 % 20) * NT + col]     = c4[0];
                attn[(r0 / 20) * 400 + (r0 % 20) * NT + col + 1] = c4[1];
                attn[(r1 / 20) * 400 + (r1 % 20) * NT + col]     = c4[2];
                attn[(r1 / 20) * 400 + (r1 % 20) * NT + col + 1] = c4[3];
            }
        }
    }
    __syncthreads();

    if (tid < 80) {
        float* row = attn + (tid / 20) * 400 + (tid % 20) * NT;
        float m = -1e30f;
#pragma unroll
        for (int t = 0; t < NT; t++) m = fmaxf(m, row[t]);
        float ssum = 0.f;
#pragma unroll
        for (int t = 0; t < NT; t++) {
            float e = expf((row[t] - m) * SCALE);
            row[t] = e; ssum += e;
        }
        float inv = 1.f / ssum;
#pragma unroll
        for (int t = 0; t < NT; t++) row[t] *= inv;
    }
    __syncthreads();

    // val slice -> g_val
    for (int idx = tid; idx < 4 * NT * NVD; idx += 256) {
        int hh = idx / 320, r = idx % 320;
        int s = r >> 4, vd = r & 15;
        const float* arow = attn + hh * 400 + s * NT;
        float acc = 0.f;
#pragma unroll
        for (int t = 0; t < NT; t++)
            acc += arow[t] * XV[t * 64 + hh * 16 + vd];
        g_val[(((size_t)b * NSEQ + n) * NT + s) * NREPR + (chunk * 4 + hh) * NVD + vd] = acc;
    }
}

// =========================================================================
// k_pool: per (n, b): key = tanh(val@Wk+bk), w = softmax(qvec.key*SCALE),
//         repr = w @ val. Small smem -> high occupancy.
// =========================================================================
__global__ void __launch_bounds__(256) k_pool(
    const float* __restrict__ Wk, const float* __restrict__ bk,
    const float* __restrict__ qvec)
{
    __shared__ float val[NT * NREPR];
    __shared__ float key[NT * NQD];
    __shared__ float wraw[NT], wbuf[NT];

    const int n = blockIdx.x, b = blockIdx.y, tid = threadIdx.x;
    const float* vsrc = g_val + ((size_t)b * NSEQ + n) * NT * NREPR;

    for (int j = tid; j < NT * NREPR / 4; j += 256)
        ((float4*)val)[j] = ((const float4*)vsrc)[j];
    __syncthreads();

    if (tid < NQD) {
        const int q = tid;
        float acc[NT];
        float bq = bk[q];
#pragma unroll
        for (int s = 0; s < NT; s++) acc[s] = bq;
        for (int rb = 0; rb < NREPR; rb += 4) {
            float w0 = __ldg(&Wk[(rb + 0) * NQD + q]);
            float w1 = __ldg(&Wk[(rb + 1) * NQD + q]);
            float w2 = __ldg(&Wk[(rb + 2) * NQD + q]);
            float w3 = __ldg(&Wk[(rb + 3) * NQD + q]);
#pragma unroll
            for (int s = 0; s < NT; s++) {
                float4 v4 = *(const float4*)&val[s * NREPR + rb];
                acc[s] += v4.x * w0 + v4.y * w1 + v4.z * w2 + v4.w * w3;
            }
        }
#pragma unroll
        for (int s = 0; s < NT; s++) key[s * NQD + tid] = tanhf(acc[s]);
    }
    __syncthreads();
    if (tid < NT) {
        float acc = 0.f;
        for (int q = 0; q < NQD; q++) acc += qvec[q] * key[tid * NQD + q];
        wraw[tid] = acc * SCALE;
    }
    __syncthreads();
    if (tid < NT) {
        float m = -1e30f;
#pragma unroll
        for (int s = 0; s < NT; s++) m = fmaxf(m, wraw[s]);
        float ssum = 0.f;
#pragma unroll
        for (int s = 0; s < NT; s++) ssum += expf(wraw[s] - m);
        wbuf[tid] = expf(wraw[tid] - m) / ssum;
    }
    __syncthreads();
    {
        float acc = 0.f;
#pragma unroll
        for (int s = 0; s < NT; s++) acc += wbuf[s] * val[s * NREPR + tid];
        g_reprs[((size_t)b * NSEQ + n) * NREPR + tid] = acc;
    }
}

// =========================================================================
// k_news: q read from precomputed g_qn; rest unchanged (R4-lineage)
// =========================================================================
#define NEWS_SMEM_BYTES (42064 * 4)

__global__ void __launch_bounds__(256, 1) k_news(
    const float* __restrict__ Wv,
    const float* __restrict__ Wk, const float* __restrict__ bk,
    const float* __restrict__ qn, float* __restrict__ out)
{
    extern __shared__ float sm[];
    float* X     = sm;
    float* QK    = sm + 12800;
    float* val   = sm + 25600;
    float* attn  = sm + 38400;
    float* xv    = sm + 40900;
    float* user  = sm + 41700;
    float* score = sm + 41956;
    float* wbuf  = sm + 41964;
    float* wraw  = sm + 42014;

    const int b = blockIdx.x, tid = threadIdx.x;

    for (int i = tid; i < NHIS * NREPR; i += 256)
        X[i] = g_reprs[((size_t)b * NSEQ + NCDD) * NREPR + i];

    for (int h = 0; h < NH; h++) {
        __syncthreads();
        // q from precomputed table (bf16 -> f32)
        for (int i = tid; i < NHIS * NREPR; i += 256) {
            int s = i >> 8, e = i & 255;
            QK[i] = __bfloat162float(
                g_qn[((size_t)b * NHIS + s) * NN + h * NREPR + e]);
        }
        __syncthreads();
        if (tid < 100) {
            int s0 = (tid / 10) * 5, t0 = (tid % 10) * 5;
            float a5[5][5];
#pragma unroll
            for (int i = 0; i < 5; i++)
#pragma unroll
                for (int j = 0; j < 5; j++) a5[i][j] = 0.f;
            for (int e = 0; e < NREPR; e += 4) {
                float4 q4[5];
#pragma unroll
                for (int i = 0; i < 5; i++) q4[i] = *(const float4*)&QK[(s0 + i) * NREPR + e];
#pragma unroll
                for (int j = 0; j < 5; j++) {
                    float4 x4 = *(const float4*)&X[(t0 + j) * NREPR + e];
#pragma unroll
                    for (int i = 0; i < 5; i++)
                        a5[i][j] += q4[i].x * x4.x + q4[i].y * x4.y
                                  + q4[i].z * x4.z + q4[i].w * x4.w;
                }
            }
#pragma unroll
            for (int i = 0; i < 5; i++)
#pragma unroll
                for (int j = 0; j < 5; j++)
                    attn[(s0 + i) * NHIS + (t0 + j)] = a5[i][j];
        }
        __syncthreads();
        if (tid < NHIS) {
            float m = -1e30f;
            for (int t = 0; t < NHIS; t++) m = fmaxf(m, attn[tid * NHIS + t]);
            float ssum = 0.f;
            for (int t = 0; t < NHIS; t++) {
                float e = expf((attn[tid * NHIS + t] - m) * SCALE);
                attn[tid * NHIS + t] = e; ssum += e;
            }
            float inv = 1.f / ssum;
            for (int t = 0; t < NHIS; t++) attn[tid * NHIS + t] *= inv;
        }
        for (int idx = tid; idx < NHIS * NVD; idx += 256) {
            int t = idx / NVD, vd = idx % NVD;
            const float* Wvh = Wv + (size_t)h * NREPR * NVD + vd;
            float acc = 0.f;
            for (int fb = 0; fb < NREPR; fb += 4) {
                float4 x4 = *(const float4*)&X[t * NREPR + fb];
                acc += x4.x * __ldg(&Wvh[(size_t)(fb + 0) * NVD])
                     + x4.y * __ldg(&Wvh[(size_t)(fb + 1) * NVD])
                     + x4.z * __ldg(&Wvh[(size_t)(fb + 2) * NVD])
                     + x4.w * __ldg(&Wvh[(size_t)(fb + 3) * NVD]);
            }
            xv[idx] = acc;
        }
        __syncthreads();
        for (int idx = tid; idx < NHIS * NVD; idx += 256) {
            int s = idx / NVD, vd = idx % NVD;
            float acc = 0.f;
            for (int t = 0; t < NHIS; t++) acc += attn[s * NHIS + t] * xv[t * NVD + vd];
            val[s * NREPR + h * NVD + vd] = acc;
        }
    }
    __syncthreads();
    if (tid < NQD) {
        const int q = tid;
        float acc[NHIS];
        float bq = bk[q];
#pragma unroll
        for (int s = 0; s < NHIS; s++) acc[s] = bq;
        for (int rb = 0; rb < NREPR; rb += 4) {
            float w0 = __ldg(&Wk[(rb + 0) * NQD + q]);
            float w1 = __ldg(&Wk[(rb + 1) * NQD + q]);
            float w2 = __ldg(&Wk[(rb + 2) * NQD + q]);
            float w3 = __ldg(&Wk[(rb + 3) * NQD + q]);
#pragma unroll 10
            for (int s = 0; s < NHIS; s++) {
                float4 v4 = *(const float4*)&val[s * NREPR + rb];
                acc[s] += v4.x * w0 + v4.y * w1 + v4.z * w2 + v4.w * w3;
            }
        }
        for (int s = 0; s < NHIS; s++) QK[s * NQD + q] = tanhf(acc[s]);
    }
    __syncthreads();
    if (tid < NHIS) {
        float acc = 0.f;
        for (int q = 0; q < NQD; q++) acc += qn[q] * QK[tid * NQD + q];
        wraw[tid] = acc * SCALE;
    }
    __syncthreads();
    if (tid < NHIS) {
        float m = -1e30f;
        for (int s = 0; s < NHIS; s++) m = fmaxf(m, wraw[s]);
        float ssum = 0.f;
        for (int s = 0; s < NHIS; s++) ssum += expf(wraw[s] - m);
        wbuf[tid] = expf(wraw[tid] - m) / ssum;
    }
    __syncthreads();
    {
        float acc = 0.f;
        for (int s = 0; s < NHIS; s++) acc += wbuf[s] * val[s * NREPR + tid];
        user[tid] = acc;
    }
    __syncthreads();
    {
        const int wid2 = tid >> 5, lane = tid & 31;
        if (wid2 < NCDD) {
            float acc = 0.f;
            for (int r = lane; r < NREPR; r += 32)
                acc += g_reprs[((size_t)b * NSEQ + wid2) * NREPR + r] * user[r];
#pragma unroll
            for (int o = 16; o; o >>= 1) acc += __shfl_down_sync(0xffffffffu, acc, o);
            if (lane == 0) score[wid2] = acc;
        }
    }
    __syncthreads();
    if (tid < NCDD) {
        float m = -1e30f;
#pragma unroll
        for (int c = 0; c < NCDD; c++) m = fmaxf(m, score[c]);
        float ssum = 0.f;
#pragma unroll
        for (int c = 0; c < NCDD; c++) ssum += expf(score[c] - m);
        out[(size_t)b * NCDD + tid] = score[tid] - m - logf(ssum);
    }
}

// =========================================================================
// launch
// =========================================================================
extern "C" void kernel_launch(void* const* d_in, const int* in_sizes, int n_in,
                              void* d_out, int out_size)
{
    const int*   cand = (const int*)  d_in[0];
    const int*   clk  = (const int*)  d_in[1];
    const float* emb  = (const float*)d_in[2];
    const float* Wq_w = (const float*)d_in[3];
    const float* Wv_w = (const float*)d_in[4];
    const float* Wk_w = (const float*)d_in[5];
    const float* bk_w = (const float*)d_in[6];
    const float* qw   = (const float*)d_in[7];
    const float* Wq_n = (const float*)d_in[8];
    const float* Wv_n = (const float*)d_in[9];
    const float* Wk_n = (const float*)d_in[10];
    const float* bk_n = (const float*)d_in[11];
    const float* qn   = (const float*)d_in[12];
    float* out = (float*)d_out;

    cudaFuncSetAttribute(k_attn, cudaFuncAttributeMaxDynamicSharedMemorySize, ATTN_SMEM_BYTES);
    cudaFuncSetAttribute(k_news, cudaFuncAttributeMaxDynamicSharedMemorySize, NEWS_SMEM_BYTES);

    k_cvt<<<(int)(((size_t)NVPAD * KTOT + 255) / 256), 256>>>(emb);
    k_packb_q<<<(int)(((size_t)NCQ * KSEG + 255) / 256), 256>>>(Wq_w);
    k_packb_ev<<<(int)(((size_t)NCEV * KTOT + 255) / 256), 256>>>(Wv_w);
    k_packb_n<<<(int)(((size_t)NN * KN + 255) / 256), 256>>>(Wq_n);
    k_gemm_t<0><<<dim3(NCQ / TN, NVPAD / TM), 256>>>();
    k_gemm_t<1><<<dim3(NCEV / TN, NVPAD / TM), 256>>>();
    k_attn<<<dim3(NSEQ * 4, NB), 256, ATTN_SMEM_BYTES>>>(cand, clk, emb);
    k_pool<<<dim3(NSEQ, NB), 256>>>(Wk_w, bk_w, qw);
    k_cvtrep<<<(int)(((size_t)MN * KN + 255) / 256), 256>>>();
    k_gemm_t<2><<<dim3(NN / TN, MN / TM), 256>>>();
    k_news<<<NB, 256, NEWS_SMEM_BYTES>>>(Wv_n, Wk_n, bk_n, qn, out);
}

// round 9
// speedup vs baseline: 6.8329x; 1.1545x over previous
#include <cuda_runtime.h>
#include <cuda_bf16.h>
#include <math.h>
#include <stdint.h>

// ---------------- problem constants ----------------
#define NV    50000
#define ND    300
#define NH    16
#define NVD   16
#define NQD   200
#define NT    20
#define NHIS  50
#define NCDD  5
#define NB    256
#define NREPR 256
#define NSEQ  55
#define SCALE 0.05773502691896258f

// GEMM padded dims
#define NVPAD 50048
#define KSEG  320
#define KTOT  960
#define QSTRIDE 304
#define NCQ   4864
#define NCEV  256
#define TM    128
#define TN    128
#define BKK   32
#define APAD  40
#define MN    12800
#define NN    4096
#define KN    256

// ---------------- device scratch ----------------
__device__ __nv_bfloat16 g_q16[(size_t)NV * NCQ];
__device__ float         g_ev[(size_t)NV * NCEV];
__device__ float         g_reprs[NB * NSEQ * NREPR];
__device__ float         g_val[(size_t)NB * NSEQ * NT * NREPR];
__device__ __nv_bfloat16 g_A2[(size_t)NVPAD * KTOT];
__device__ __nv_bfloat16 g_B1[(size_t)NCQ * KSEG];
__device__ __nv_bfloat16 g_B2[(size_t)NCEV * KTOT];
__device__ __nv_bfloat16 g_An[(size_t)MN * KN];
__device__ __nv_bfloat16 g_Bn[(size_t)NN * KN];
__device__ __nv_bfloat16 g_qn[(size_t)MN * NN];

// ---------------- helpers ----------------
__device__ __forceinline__ uint32_t smem_u32(const void* p) {
    uint32_t a;
    asm("{ .reg .u64 t; cvta.to.shared.u64 t, %1; cvt.u32.u64 %0, t; }" : "=r"(a) : "l"(p));
    return a;
}
__device__ __forceinline__ void cp_async16(uint32_t s, const void* g) {
    asm volatile("cp.async.cg.shared.global [%0], [%1], 16;" :: "r"(s), "l"(g));
}
#define CP_COMMIT() asm volatile("cp.async.commit_group;" ::: "memory")
#define CP_WAIT1()  asm volatile("cp.async.wait_group 1;" ::: "memory")
#define CP_WAIT0()  asm volatile("cp.async.wait_group 0;" ::: "memory")

__device__ __forceinline__ void mma16816(float* c, const uint32_t* a, const uint32_t* b) {
    asm volatile(
        "mma.sync.aligned.m16n8k16.row.col.f32.bf16.bf16.f32 "
        "{%0,%1,%2,%3}, {%4,%5,%6,%7}, {%8,%9}, {%0,%1,%2,%3};"
        : "+f"(c[0]), "+f"(c[1]), "+f"(c[2]), "+f"(c[3])
        : "r"(a[0]), "r"(a[1]), "r"(a[2]), "r"(a[3]), "r"(b[0]), "r"(b[1]));
}

// =========================================================================
// prep kernels
// =========================================================================
__global__ void k_cvt(const float* __restrict__ emb)
{
    uint32_t idx = blockIdx.x * 256u + threadIdx.x;
    if (idx >= (uint32_t)NVPAD * KTOT) return;
    uint32_t v = idx / KTOT, kk = idx % KTOT;
    uint32_t seg = kk / KSEG, k = kk % KSEG;
    float a = (v < NV && k < ND) ? emb[(size_t)v * ND + k] : 0.f;
    __nv_bfloat16 hi = __float2bfloat16(a);
    g_A2[idx] = (seg == 2) ? __float2bfloat16(a - __bfloat162float(hi)) : hi;
}

__global__ void k_packb_q(const float* __restrict__ Wq)
{
    uint32_t idx = blockIdx.x * 256u + threadIdx.x;
    if (idx >= (uint32_t)NCQ * KSEG) return;
    uint32_t c = idx / KSEG, k = idx % KSEG;
    uint32_t h = c / QSTRIDE, e = c % QSTRIDE;
    float a = (e < ND && k < ND) ? Wq[((size_t)h * ND + k) * ND + e] : 0.f;
    g_B1[idx] = __float2bfloat16(a);
}

__global__ void k_packb_ev(const float* __restrict__ Wv)
{
    uint32_t idx = blockIdx.x * 256u + threadIdx.x;
    if (idx >= (uint32_t)NCEV * KTOT) return;
    uint32_t c = idx / KTOT, kk = idx % KTOT;
    uint32_t seg = kk / KSEG, k = kk % KSEG;
    uint32_t h = c >> 4, vd = c & 15;
    float a = (k < ND) ? Wv[((size_t)h * ND + k) * NVD + vd] : 0.f;
    __nv_bfloat16 hi = __float2bfloat16(a);
    g_B2[idx] = (seg == 1) ? __float2bfloat16(a - __bfloat162float(hi)) : hi;
}

__global__ void k_packb_n(const float* __restrict__ Wqn)
{
    uint32_t idx = blockIdx.x * 256u + threadIdx.x;
    if (idx >= (uint32_t)NN * KN) return;
    uint32_t c = idx / KN, k = idx % KN;
    uint32_t h = c >> 8, e = c & 255;
    g_Bn[idx] = __float2bfloat16(Wqn[((size_t)h * NREPR + k) * NREPR + e]);
}

__global__ void k_cvtrep()
{
    uint32_t idx = blockIdx.x * 256u + threadIdx.x;
    if (idx >= (uint32_t)MN * KN) return;
    uint32_t r = idx / KN, c = idx % KN;
    uint32_t b = r / NHIS, s = r % NHIS;
    g_An[idx] = __float2bfloat16(g_reprs[((size_t)b * NSEQ + NCDD + s) * NREPR + c]);
}

// =========================================================================
// unified tensor-core GEMM (verified skeleton)
// =========================================================================
template<int MODE>
__global__ void __launch_bounds__(256) k_gemm_t()
{
    constexpr int KA  = (MODE == 2) ? KN : KTOT;
    constexpr int KB  = (MODE == 0) ? KSEG : (MODE == 1) ? KTOT : KN;
    constexpr int NST = (MODE == 0) ? 10 : (MODE == 1) ? 30 : 8;
    const __nv_bfloat16* Ap = (MODE == 2) ? g_An : g_A2;
    const __nv_bfloat16* Bp = (MODE == 0) ? g_B1 : (MODE == 1) ? g_B2 : g_Bn;
    const int maxM = (MODE == 2) ? MN : NV;

    __shared__ __nv_bfloat16 As[2][TM][APAD];
    __shared__ __nv_bfloat16 Bs[2][TN][APAD];
    const int tid = threadIdx.x;
    const int wid = tid >> 5, lid = tid & 31;
    const int wm = wid & 3, wn = wid >> 2;
    const int g = lid >> 2, t = lid & 3;
    const int c0 = blockIdx.x * TN;
    const int v0 = blockIdx.y * TM;

    auto ldst = [&](int kt) {
        const int buf = kt & 1;
        const size_t k0 = (size_t)kt * BKK;
#pragma unroll
        for (int i = 0; i < 2; i++) {
            int j = tid + i * 256;
            int row = j >> 2, q = j & 3;
            cp_async16(smem_u32(&As[buf][row][q * 8]),
                       Ap + (size_t)(v0 + row) * KA + k0 + q * 8);
            cp_async16(smem_u32(&Bs[buf][row][q * 8]),
                       Bp + (size_t)(c0 + row) * KB + k0 + q * 8);
        }
    };

    float acc[2][8][4];
#pragma unroll
    for (int f = 0; f < 2; f++)
#pragma unroll
        for (int n = 0; n < 8; n++)
#pragma unroll
            for (int x = 0; x < 4; x++) acc[f][n][x] = 0.f;

    ldst(0);
    CP_COMMIT();
    for (int kt = 0; kt < NST; kt++) {
        const int buf = kt & 1;
        if (kt < NST - 1) { ldst(kt + 1); CP_COMMIT(); CP_WAIT1(); }
        else              { CP_WAIT0(); }
        __syncthreads();
#pragma unroll
        for (int ks = 0; ks < BKK; ks += 16) {
            uint32_t af[2][4];
#pragma unroll
            for (int f = 0; f < 2; f++) {
                const int rb = wm * 32 + f * 16;
                af[f][0] = *(const uint32_t*)&As[buf][rb + g][ks + 2 * t];
                af[f][1] = *(const uint32_t*)&As[buf][rb + g + 8][ks + 2 * t];
                af[f][2] = *(const uint32_t*)&As[buf][rb + g][ks + 2 * t + 8];
                af[f][3] = *(const uint32_t*)&As[buf][rb + g + 8][ks + 2 * t + 8];
            }
            uint32_t bf_[8][2];
#pragma unroll
            for (int n = 0; n < 8; n++) {
                const int nb = wn * 64 + n * 8;
                bf_[n][0] = *(const uint32_t*)&Bs[buf][nb + g][ks + 2 * t];
                bf_[n][1] = *(const uint32_t*)&Bs[buf][nb + g][ks + 2 * t + 8];
            }
#pragma unroll
            for (int f = 0; f < 2; f++)
#pragma unroll
                for (int n = 0; n < 8; n++)
                    mma16816(acc[f][n], af[f], bf_[n]);
        }
        __syncthreads();
    }

#pragma unroll
    for (int f = 0; f < 2; f++) {
        const int m = v0 + wm * 32 + f * 16 + g;
#pragma unroll
        for (int n = 0; n < 8; n++) {
            const int col = c0 + wn * 64 + n * 8 + 2 * t;
            if (MODE == 1) {
                if (m < maxM)
                    *(float2*)&g_ev[(size_t)m * NCEV + col] = make_float2(acc[f][n][0], acc[f][n][1]);
                if (m + 8 < maxM)
                    *(float2*)&g_ev[(size_t)(m + 8) * NCEV + col] = make_float2(acc[f][n][2], acc[f][n][3]);
            } else {
                __nv_bfloat16* dst = (MODE == 0) ? g_q16 : g_qn;
                const int ldc = (MODE == 0) ? NCQ : NN;
                if (m < maxM) {
                    __nv_bfloat162 pr = __floats2bfloat162_rn(acc[f][n][0], acc[f][n][1]);
                    *(__nv_bfloat162*)&dst[(size_t)m * ldc + col] = pr;
                }
                if (m + 8 < maxM) {
                    __nv_bfloat162 pr = __floats2bfloat162_rn(acc[f][n][2], acc[f][n][3]);
                    *(__nv_bfloat162*)&dst[(size_t)(m + 8) * ldc + col] = pr;
                }
            }
        }
    }
}

// =========================================================================
// k_attn: one CTA per (2-head chunk, n, b). cp.async gathers, 4 CTAs/SM.
// smem bytes:
//   As   [48][312] bf16 @ 0      29952  (rows 40-47 zeroed)
//   Xs   [24][312] bf16 @ 29952  14976  (rows 20-23 zeroed; from g_A2 seg0)
//   XV   [20][32]  f32  @ 44928  2560
//   attn [2][20][20] f32 @ 47488 3200
//   tok  [20] int @ 50688        80
// total 50768 -> 4 CTAs/SM
// =========================================================================
#define XSTR 312
#define ATTN_SMEM_BYTES 50768

__global__ void __launch_bounds__(256, 4) k_attn(
    const int* __restrict__ cand, const int* __restrict__ clk)
{
    extern __shared__ char smw[];
    __nv_bfloat16* As = (__nv_bfloat16*)(smw);
    __nv_bfloat16* Xs = (__nv_bfloat16*)(smw + 29952);
    float* XV   = (float*)(smw + 44928);
    float* attn = (float*)(smw + 47488);
    int*   tok  = (int*)(smw + 50688);

    const int nx = blockIdx.x;
    const int n = nx >> 3, chunk = nx & 7;      // chunk of 2 heads
    const int b = blockIdx.y, tid = threadIdx.x;
    const int wid = tid >> 5, lid = tid & 31;
    const int g = lid >> 2, t4 = lid & 3;

    if (tid < NT) {
        tok[tid] = (n < NCDD) ? cand[((size_t)b * NCDD + n) * NT + tid]
                              : clk[((size_t)b * NHIS + (n - NCDD)) * NT + tid];
    }
    // zero tail rows: As rows 40-47 (4992B), Xs rows 20-23 (2496B)
    for (int j = tid; j < (4992 + 2496) / 8; j += 256) {
        if (j < 624) ((uint64_t*)(As + 40 * XSTR))[j] = 0ull;
        else         ((uint64_t*)(Xs + 20 * XSTR))[j - 624] = 0ull;
    }
    __syncthreads();

    // async gathers: Q (40 rows x 38), X (20 rows x 38), XV (20 rows x 8)
    for (int j = tid; j < 40 * 38; j += 256) {
        int row = j / 38, q = j % 38;
        int s = row % 20, h2 = row / 20;
        cp_async16(smem_u32(&As[row * XSTR + q * 8]),
                   g_q16 + (size_t)tok[s] * NCQ + (chunk * 2 + h2) * QSTRIDE + q * 8);
    }
    for (int j = tid; j < 20 * 38; j += 256) {
        int s = j / 38, q = j % 38;
        cp_async16(smem_u32(&Xs[s * XSTR + q * 8]),
                   g_A2 + (size_t)tok[s] * KTOT + q * 8);
    }
    for (int j = tid; j < 20 * 8; j += 256) {
        int s = j >> 3, q = j & 7;
        cp_async16(smem_u32(&XV[s * 32 + q * 4]),
                   g_ev + (size_t)tok[s] * NCEV + chunk * 32 + q * 4);
    }
    CP_COMMIT();
    CP_WAIT0();
    __syncthreads();

    // logits mma: M=48(3 m16), N=24(3 n8), K=304(19 k16); 9 tiles over 8 warps
#pragma unroll
    for (int rep = 0; rep < 2; rep++) {
        int id = wid + rep * 8;
        if (id < 9) {
            int mt = id / 3, nt = id % 3;
            float c4[4] = {0.f, 0.f, 0.f, 0.f};
#pragma unroll
            for (int ks = 0; ks < 19; ks++) {
                const int kk = ks * 16;
                uint32_t a[4], bb[2];
                a[0] = *(const uint32_t*)&As[(mt * 16 + g) * XSTR + kk + 2 * t4];
                a[1] = *(const uint32_t*)&As[(mt * 16 + g + 8) * XSTR + kk + 2 * t4];
                a[2] = *(const uint32_t*)&As[(mt * 16 + g) * XSTR + kk + 2 * t4 + 8];
                a[3] = *(const uint32_t*)&As[(mt * 16 + g + 8) * XSTR + kk + 2 * t4 + 8];
                bb[0] = *(const uint32_t*)&Xs[(nt * 8 + g) * XSTR + kk + 2 * t4];
                bb[1] = *(const uint32_t*)&Xs[(nt * 8 + g) * XSTR + kk + 2 * t4 + 8];
                mma16816(c4, a, bb);
            }
            int r0 = mt * 16 + g, r1 = r0 + 8;
            int col = nt * 8 + 2 * t4;
            if (col < NT) {
                if (r0 < 40) {
                    attn[(r0 / 20) * 400 + (r0 % 20) * NT + col]     = c4[0];
                    attn[(r0 / 20) * 400 + (r0 % 20) * NT + col + 1] = c4[1];
                }
                if (r1 < 40) {
                    attn[(r1 / 20) * 400 + (r1 % 20) * NT + col]     = c4[2];
                    attn[(r1 / 20) * 400 + (r1 % 20) * NT + col + 1] = c4[3];
                }
            }
        }
    }
    __syncthreads();

    if (tid < 40) {
        float* row = attn + (tid / 20) * 400 + (tid % 20) * NT;
        float m = -1e30f;
#pragma unroll
        for (int t = 0; t < NT; t++) m = fmaxf(m, row[t]);
        float ssum = 0.f;
#pragma unroll
        for (int t = 0; t < NT; t++) {
            float e = expf((row[t] - m) * SCALE);
            row[t] = e; ssum += e;
        }
        float inv = 1.f / ssum;
#pragma unroll
        for (int t = 0; t < NT; t++) row[t] *= inv;
    }
    __syncthreads();

    // val slice (2 heads x 20 s x 16 vd = 640) -> g_val
    for (int idx = tid; idx < 2 * NT * NVD; idx += 256) {
        int hh = idx / 320, r = idx % 320;
        int s = r >> 4, vd = r & 15;
        const float* arow = attn + hh * 400 + s * NT;
        float acc = 0.f;
#pragma unroll
        for (int t = 0; t < NT; t++)
            acc += arow[t] * XV[t * 32 + hh * 16 + vd];
        g_val[(((size_t)b * NSEQ + n) * NT + s) * NREPR + (chunk * 2 + hh) * NVD + vd] = acc;
    }
}

// =========================================================================
// k_pool (unchanged)
// =========================================================================
__global__ void __launch_bounds__(256) k_pool(
    const float* __restrict__ Wk, const float* __restrict__ bk,
    const float* __restrict__ qvec)
{
    __shared__ float val[NT * NREPR];
    __shared__ float key[NT * NQD];
    __shared__ float wraw[NT], wbuf[NT];

    const int n = blockIdx.x, b = blockIdx.y, tid = threadIdx.x;
    const float* vsrc = g_val + ((size_t)b * NSEQ + n) * NT * NREPR;

    for (int j = tid; j < NT * NREPR / 4; j += 256)
        ((float4*)val)[j] = ((const float4*)vsrc)[j];
    __syncthreads();

    if (tid < NQD) {
        const int q = tid;
        float acc[NT];
        float bq = bk[q];
#pragma unroll
        for (int s = 0; s < NT; s++) acc[s] = bq;
        for (int rb = 0; rb < NREPR; rb += 4) {
            float w0 = __ldg(&Wk[(rb + 0) * NQD + q]);
            float w1 = __ldg(&Wk[(rb + 1) * NQD + q]);
            float w2 = __ldg(&Wk[(rb + 2) * NQD + q]);
            float w3 = __ldg(&Wk[(rb + 3) * NQD + q]);
#pragma unroll
            for (int s = 0; s < NT; s++) {
                float4 v4 = *(const float4*)&val[s * NREPR + rb];
                acc[s] += v4.x * w0 + v4.y * w1 + v4.z * w2 + v4.w * w3;
            }
        }
#pragma unroll
        for (int s = 0; s < NT; s++) key[s * NQD + tid] = tanhf(acc[s]);
    }
    __syncthreads();
    if (tid < NT) {
        float acc = 0.f;
        for (int q = 0; q < NQD; q++) acc += qvec[q] * key[tid * NQD + q];
        wraw[tid] = acc * SCALE;
    }
    __syncthreads();
    if (tid < NT) {
        float m = -1e30f;
#pragma unroll
        for (int s = 0; s < NT; s++) m = fmaxf(m, wraw[s]);
        float ssum = 0.f;
#pragma unroll
        for (int s = 0; s < NT; s++) ssum += expf(wraw[s] - m);
        wbuf[tid] = expf(wraw[tid] - m) / ssum;
    }
    __syncthreads();
    {
        float acc = 0.f;
#pragma unroll
        for (int s = 0; s < NT; s++) acc += wbuf[s] * val[s * NREPR + tid];
        g_reprs[((size_t)b * NSEQ + n) * NREPR + tid] = acc;
    }
}

// =========================================================================
// k_news (unchanged)
// =========================================================================
#define NEWS_SMEM_BYTES (42064 * 4)

__global__ void __launch_bounds__(256, 1) k_news(
    const float* __restrict__ Wv,
    const float* __restrict__ Wk, const float* __restrict__ bk,
    const float* __restrict__ qn, float* __restrict__ out)
{
    extern __shared__ float sm[];
    float* X     = sm;
    float* QK    = sm + 12800;
    float* val   = sm + 25600;
    float* attn  = sm + 38400;
    float* xv    = sm + 40900;
    float* user  = sm + 41700;
    float* score = sm + 41956;
    float* wbuf  = sm + 41964;
    float* wraw  = sm + 42014;

    const int b = blockIdx.x, tid = threadIdx.x;

    for (int i = tid; i < NHIS * NREPR; i += 256)
        X[i] = g_reprs[((size_t)b * NSEQ + NCDD) * NREPR + i];

    for (int h = 0; h < NH; h++) {
        __syncthreads();
        for (int i = tid; i < NHIS * NREPR; i += 256) {
            int s = i >> 8, e = i & 255;
            QK[i] = __bfloat162float(
                g_qn[((size_t)b * NHIS + s) * NN + h * NREPR + e]);
        }
        __syncthreads();
        if (tid < 100) {
            int s0 = (tid / 10) * 5, t0 = (tid % 10) * 5;
            float a5[5][5];
#pragma unroll
            for (int i = 0; i < 5; i++)
#pragma unroll
                for (int j = 0; j < 5; j++) a5[i][j] = 0.f;
            for (int e = 0; e < NREPR; e += 4) {
                float4 q4[5];
#pragma unroll
                for (int i = 0; i < 5; i++) q4[i] = *(const float4*)&QK[(s0 + i) * NREPR + e];
#pragma unroll
                for (int j = 0; j < 5; j++) {
                    float4 x4 = *(const float4*)&X[(t0 + j) * NREPR + e];
#pragma unroll
                    for (int i = 0; i < 5; i++)
                        a5[i][j] += q4[i].x * x4.x + q4[i].y * x4.y
                                  + q4[i].z * x4.z + q4[i].w * x4.w;
                }
            }
#pragma unroll
            for (int i = 0; i < 5; i++)
#pragma unroll
                for (int j = 0; j < 5; j++)
                    attn[(s0 + i) * NHIS + (t0 + j)] = a5[i][j];
        }
        __syncthreads();
        if (tid < NHIS) {
            float m = -1e30f;
            for (int t = 0; t < NHIS; t++) m = fmaxf(m, attn[tid * NHIS + t]);
            float ssum = 0.f;
            for (int t = 0; t < NHIS; t++) {
                float e = expf((attn[tid * NHIS + t] - m) * SCALE);
                attn[tid * NHIS + t] = e; ssum += e;
            }
            float inv = 1.f / ssum;
            for (int t = 0; t < NHIS; t++) attn[tid * NHIS + t] *= inv;
        }
        for (int idx = tid; idx < NHIS * NVD; idx += 256) {
            int t = idx / NVD, vd = idx % NVD;
            const float* Wvh = Wv + (size_t)h * NREPR * NVD + vd;
            float acc = 0.f;
            for (int fb = 0; fb < NREPR; fb += 4) {
                float4 x4 = *(const float4*)&X[t * NREPR + fb];
                acc += x4.x * __ldg(&Wvh[(size_t)(fb + 0) * NVD])
                     + x4.y * __ldg(&Wvh[(size_t)(fb + 1) * NVD])
                     + x4.z * __ldg(&Wvh[(size_t)(fb + 2) * NVD])
                     + x4.w * __ldg(&Wvh[(size_t)(fb + 3) * NVD]);
            }
            xv[idx] = acc;
        }
        __syncthreads();
        for (int idx = tid; idx < NHIS * NVD; idx += 256) {
            int s = idx / NVD, vd = idx % NVD;
            float acc = 0.f;
            for (int t = 0; t < NHIS; t++) acc += attn[s * NHIS + t] * xv[t * NVD + vd];
            val[s * NREPR + h * NVD + vd] = acc;
        }
    }
    __syncthreads();
    if (tid < NQD) {
        const int q = tid;
        float acc[NHIS];
        float bq = bk[q];
#pragma unroll
        for (int s = 0; s < NHIS; s++) acc[s] = bq;
        for (int rb = 0; rb < NREPR; rb += 4) {
            float w0 = __ldg(&Wk[(rb + 0) * NQD + q]);
            float w1 = __ldg(&Wk[(rb + 1) * NQD + q]);
            float w2 = __ldg(&Wk[(rb + 2) * NQD + q]);
            float w3 = __ldg(&Wk[(rb + 3) * NQD + q]);
#pragma unroll 10
            for (int s = 0; s < NHIS; s++) {
                float4 v4 = *(const float4*)&val[s * NREPR + rb];
                acc[s] += v4.x * w0 + v4.y * w1 + v4.z * w2 + v4.w * w3;
            }
        }
        for (int s = 0; s < NHIS; s++) QK[s * NQD + q] = tanhf(acc[s]);
    }
    __syncthreads();
    if (tid < NHIS) {
        float acc = 0.f;
        for (int q = 0; q < NQD; q++) acc += qn[q] * QK[tid * NQD + q];
        wraw[tid] = acc * SCALE;
    }
    __syncthreads();
    if (tid < NHIS) {
        float m = -1e30f;
        for (int s = 0; s < NHIS; s++) m = fmaxf(m, wraw[s]);
        float ssum = 0.f;
        for (int s = 0; s < NHIS; s++) ssum += expf(wraw[s] - m);
        wbuf[tid] = expf(wraw[tid] - m) / ssum;
    }
    __syncthreads();
    {
        float acc = 0.f;
        for (int s = 0; s < NHIS; s++) acc += wbuf[s] * val[s * NREPR + tid];
        user[tid] = acc;
    }
    __syncthreads();
    {
        const int wid2 = tid >> 5, lane = tid & 31;
        if (wid2 < NCDD) {
            float acc = 0.f;
            for (int r = lane; r < NREPR; r += 32)
                acc += g_reprs[((size_t)b * NSEQ + wid2) * NREPR + r] * user[r];
#pragma unroll
            for (int o = 16; o; o >>= 1) acc += __shfl_down_sync(0xffffffffu, acc, o);
            if (lane == 0) score[wid2] = acc;
        }
    }
    __syncthreads();
    if (tid < NCDD) {
        float m = -1e30f;
#pragma unroll
        for (int c = 0; c < NCDD; c++) m = fmaxf(m, score[c]);
        float ssum = 0.f;
#pragma unroll
        for (int c = 0; c < NCDD; c++) ssum += expf(score[c] - m);
        out[(size_t)b * NCDD + tid] = score[tid] - m - logf(ssum);
    }
}

// =========================================================================
// launch
// =========================================================================
extern "C" void kernel_launch(void* const* d_in, const int* in_sizes, int n_in,
                              void* d_out, int out_size)
{
    const int*   cand = (const int*)  d_in[0];
    const int*   clk  = (const int*)  d_in[1];
    const float* emb  = (const float*)d_in[2];
    const float* Wq_w = (const float*)d_in[3];
    const float* Wv_w = (const float*)d_in[4];
    const float* Wk_w = (const float*)d_in[5];
    const float* bk_w = (const float*)d_in[6];
    const float* qw   = (const float*)d_in[7];
    const float* Wq_n = (const float*)d_in[8];
    const float* Wv_n = (const float*)d_in[9];
    const float* Wk_n = (const float*)d_in[10];
    const float* bk_n = (const float*)d_in[11];
    const float* qn   = (const float*)d_in[12];
    float* out = (float*)d_out;

    cudaFuncSetAttribute(k_attn, cudaFuncAttributeMaxDynamicSharedMemorySize, ATTN_SMEM_BYTES);
    cudaFuncSetAttribute(k_news, cudaFuncAttributeMaxDynamicSharedMemorySize, NEWS_SMEM_BYTES);

    k_cvt<<<(int)(((size_t)NVPAD * KTOT + 255) / 256), 256>>>(emb);
    k_packb_q<<<(int)(((size_t)NCQ * KSEG + 255) / 256), 256>>>(Wq_w);
    k_packb_ev<<<(int)(((size_t)NCEV * KTOT + 255) / 256), 256>>>(Wv_w);
    k_packb_n<<<(int)(((size_t)NN * KN + 255) / 256), 256>>>(Wq_n);
    k_gemm_t<0><<<dim3(NCQ / TN, NVPAD / TM), 256>>>();
    k_gemm_t<1><<<dim3(NCEV / TN, NVPAD / TM), 256>>>();
    k_attn<<<dim3(NSEQ * 8, NB), 256, ATTN_SMEM_BYTES>>>(cand, clk);
    k_pool<<<dim3(NSEQ, NB), 256>>>(Wk_w, bk_w, qw);
    k_cvtrep<<<(int)(((size_t)MN * KN + 255) / 256), 256>>>();
    k_gemm_t<2><<<dim3(NN / TN, MN / TM), 256>>>();
    k_news<<<NB, 256, NEWS_SMEM_BYTES>>>(Wv_n, Wk_n, bk_n, qn, out);
}